// round 7
// baseline (speedup 1.0000x reference)
#include <cuda_runtime.h>
#include <mma.h>
#include <math.h>
#include <stdint.h>

using namespace nvcuda;

#define B_SZ 4
#define T_SZ 2048
#define C_SZ 1024
#define H_SZ 16
#define D_SZ 64
#define M_SZ (B_SZ * T_SZ)   // 8192

// ---------------- scratch (static device globals; no allocation) ----------------
__device__ float g_q[(size_t)B_SZ * H_SZ * T_SZ * D_SZ];   // [B,H,T,D] tf32-rounded
__device__ float g_k[(size_t)B_SZ * H_SZ * T_SZ * D_SZ];
__device__ float g_v[(size_t)B_SZ * H_SZ * T_SZ * D_SZ];
__device__ float g_ao[(size_t)B_SZ * T_SZ * C_SZ];         // attention out, tf32-rounded
__device__ float g_xr[(size_t)M_SZ * C_SZ];                // x, tf32-rounded
__device__ float g_wqkv[(size_t)C_SZ * 3 * C_SZ];          // W_qkv, tf32-rounded
__device__ float g_wout[(size_t)C_SZ * C_SZ];              // W_out, tf32-rounded

// ---------------- cp.async helpers ----------------
__device__ __forceinline__ void cp_async16(void* smem, const void* gmem) {
    uint32_t s = (uint32_t)__cvta_generic_to_shared(smem);
    asm volatile("cp.async.cg.shared.global [%0], [%1], 16;\n" :: "r"(s), "l"(gmem));
}
__device__ __forceinline__ void cp_commit() {
    asm volatile("cp.async.commit_group;\n");
}
template<int N>
__device__ __forceinline__ void cp_wait() {
    asm volatile("cp.async.wait_group %0;\n" :: "n"(N));
}

// ---------------- prep: round to tf32 in gmem ----------------
__global__ void round_copy(const float* __restrict__ src, float* __restrict__ dst, int n4) {
    int i = blockIdx.x * blockDim.x + threadIdx.x;
    if (i < n4) {
        float4 v = ((const float4*)src)[i];
        v.x = wmma::__float_to_tf32(v.x);
        v.y = wmma::__float_to_tf32(v.y);
        v.z = wmma::__float_to_tf32(v.z);
        v.w = wmma::__float_to_tf32(v.w);
        ((float4*)dst)[i] = v;
    }
}

// ---------------- GEMM v2: 256x128 CTA, 64x64 warp tiles, 3-stage ring ----------
// (unchanged from R6 — 713us known-good)
#define BM 256
#define BN 128
#define BK 32
#define GS 3
#define LDA (BK + 4)    // 36
#define LDB (BN + 4)    // 132
#define A_STG (BM * LDA)          // 9216 floats
#define B_STG (BK * LDB)          // 4224 floats
#define GEMM_SMEM_BYTES (GS * (A_STG + B_STG) * 4)   // 161280 B

__global__ void __launch_bounds__(256, 1) gemm_tf32(
    const float* __restrict__ bias, float* __restrict__ Cout,
    int M, int N, int K, int mode)
{
    extern __shared__ float gsm[];
    float* Ash = gsm;
    float* Bsh = gsm + GS * A_STG;

    const float* Aptr = (mode == 1) ? g_ao : g_xr;
    const float* Bm   = (mode == 1) ? g_wout : g_wqkv;

    int tid  = threadIdx.x;
    int warp = tid >> 5;
    int lane = tid & 31;
    int wm = warp >> 1;
    int wn = warp & 1;
    int m0 = blockIdx.y * BM;
    int n0 = blockIdx.x * BN;

    wmma::fragment<wmma::accumulator, 16, 16, 8, float> acc[4][4];
    #pragma unroll
    for (int i = 0; i < 4; i++)
        #pragma unroll
        for (int j = 0; j < 4; j++)
            wmma::fill_fragment(acc[i][j], 0.0f);

    int ar = tid >> 3,  ac = (tid & 7)  * 4;
    int br = tid >> 5,  bc = (tid & 31) * 4;

    auto load_tile = [&](int stage, int k0) {
        float* As = Ash + stage * A_STG;
        float* Bs = Bsh + stage * B_STG;
        #pragma unroll
        for (int i = 0; i < 8; i++) {
            int r = ar + i * 32;
            cp_async16(As + r * LDA + ac, Aptr + (size_t)(m0 + r) * K + k0 + ac);
        }
        #pragma unroll
        for (int i = 0; i < 4; i++) {
            int r = br + i * 8;
            cp_async16(Bs + r * LDB + bc, Bm + (size_t)(k0 + r) * N + n0 + bc);
        }
        cp_commit();
    };

    int KT = K / BK;
    load_tile(0, 0);
    load_tile(1, BK);

    for (int kt = 0; kt < KT; ++kt) {
        cp_wait<1>();
        __syncthreads();
        if (kt + 2 < KT) load_tile((kt + 2) % GS, (kt + 2) * BK);
        else             cp_commit();

        float* As = Ash + (kt % GS) * A_STG;
        float* Bs = Bsh + (kt % GS) * B_STG;

        #pragma unroll
        for (int kk = 0; kk < BK; kk += 8) {
            wmma::fragment<wmma::matrix_a, 16, 16, 8, wmma::precision::tf32, wmma::row_major> af[4];
            wmma::fragment<wmma::matrix_b, 16, 16, 8, wmma::precision::tf32, wmma::row_major> bf[4];
            #pragma unroll
            for (int i = 0; i < 4; i++)
                wmma::load_matrix_sync(af[i], As + (wm * 64 + i * 16) * LDA + kk, LDA);
            #pragma unroll
            for (int j = 0; j < 4; j++)
                wmma::load_matrix_sync(bf[j], Bs + kk * LDB + wn * 64 + j * 16, LDB);
            #pragma unroll
            for (int i = 0; i < 4; i++)
                #pragma unroll
                for (int j = 0; j < 4; j++)
                    wmma::mma_sync(acc[i][j], af[i], bf[j], acc[i][j]);
        }
    }
    __syncthreads();

    float* stg = Ash + warp * 256;
    #pragma unroll
    for (int i = 0; i < 4; i++) {
        #pragma unroll
        for (int j = 0; j < 4; j++) {
            wmma::store_matrix_sync(stg, acc[i][j], 16, wmma::mem_row_major);
            __syncwarp();
            #pragma unroll
            for (int e = 0; e < 8; e++) {
                int idx = lane + e * 32;
                int rr = idx >> 4, cc = idx & 15;
                int m = m0 + wm * 64 + i * 16 + rr;
                int n = n0 + wn * 64 + j * 16 + cc;
                float val = stg[idx] + bias[n];
                if (mode == 0) {
                    int third = n >> 10, c = n & 1023;
                    int h = c >> 6, d = c & 63;
                    int b = m >> 11, t = m & 2047;
                    float* dst = (third == 0) ? g_q : (third == 1) ? g_k : g_v;
                    dst[(((size_t)(b * H_SZ + h)) * T_SZ + t) * D_SZ + d] =
                        wmma::__float_to_tf32(val);
                } else {
                    Cout[(size_t)m * N + n] = val;
                }
            }
            __syncwarp();
        }
    }
}

// ---------------- Flash attention (causal), tf32 wmma, cp.async K/V pipeline ------
// One CTA per (b,h,128-row Q tile). 8 warps, each owns 16 rows end-to-end.
// 2-stage K/V ring: loads for kt+1 fly while kt computes.
#define AQ 128
#define AK 64
#define ALD 68
#define KV_STG (AK * ALD)                 // 4352 floats per tile
#define ATT_SMEM_FLOATS (AQ * ALD + 2 * KV_STG /*K*/ + 2 * KV_STG /*V*/ + AQ * ALD /*S*/ + AQ)
#define ATT_SMEM_BYTES  (ATT_SMEM_FLOATS * 4)   // 139,776 B -> 1 CTA/SM

__global__ void __launch_bounds__(256, 1) attn_kernel()
{
    extern __shared__ float smbuf[];
    float* Qsh  = smbuf;
    float* Ksh  = Qsh + AQ * ALD;          // 2 stages
    float* Vsh  = Ksh + 2 * KV_STG;        // 2 stages
    float* Ssh  = Vsh + 2 * KV_STG;
    float* rowl = Ssh + AQ * ALD;

    int qt = gridDim.x - 1 - blockIdx.x;   // longest tiles first
    int q0 = qt * AQ;
    int bh = blockIdx.y;
    int b = bh >> 4, h = bh & 15;

    const float* Qb = g_q + (size_t)bh * T_SZ * D_SZ;
    const float* Kb = g_k + (size_t)bh * T_SZ * D_SZ;
    const float* Vb = g_v + (size_t)bh * T_SZ * D_SZ;

    int tid  = threadIdx.x;
    int warp = tid >> 5;
    int lane = tid & 31;
    int r0 = warp * 16;

    // load Q tile via cp.async too (overlaps with init below)
    #pragma unroll
    for (int i = 0; i < 8; i++) {
        int idx = tid + i * 256;
        int r = idx >> 4, c = (idx & 15) * 4;
        cp_async16(Qsh + r * ALD + c, Qb + (size_t)(q0 + r) * D_SZ + c);
    }
    cp_commit();

    // K/V stage fill: per thread 4 f4 of K + 4 f4 of V
    int kr = tid >> 4, kc = (tid & 15) * 4;   // 16 rows per pass, 4 passes
    auto fill_kv = [&](int stage, int k0) {
        float* Ks = Ksh + stage * KV_STG;
        float* Vs = Vsh + stage * KV_STG;
        #pragma unroll
        for (int i = 0; i < 4; i++) {
            int r = kr + i * 16;
            cp_async16(Ks + r * ALD + kc, Kb + (size_t)(k0 + r) * D_SZ + kc);
            cp_async16(Vs + r * ALD + kc, Vb + (size_t)(k0 + r) * D_SZ + kc);
        }
        cp_commit();
    };

    wmma::fragment<wmma::accumulator, 16, 16, 8, float> oacc[4];
    #pragma unroll
    for (int j = 0; j < 4; j++) wmma::fill_fragment(oacc[j], 0.f);

    float lacc = 0.f;
    int rl = lane >> 1, half = lane & 1;
    int myrow = r0 + rl;
    int qi = q0 + myrow;

    int nkt = 2 * qt + 2;
    fill_kv(0, 0);     // group: {Q, KV0}

    for (int kt = 0; kt < nkt; ++kt) {
        int s = kt & 1;
        __syncthreads();                    // all warps done with buffers of kt-1
        if (kt + 1 < nkt) {
            fill_kv(s ^ 1, (kt + 1) * AK);  // prefetch next into the freed stage
            cp_wait<1>();                   // stage kt (and Q) landed
        } else {
            cp_wait<0>();
        }
        __syncthreads();                    // visibility of stage kt to all warps

        float* Ks = Ksh + s * KV_STG;
        float* Vs = Vsh + s * KV_STG;
        int k0 = kt * AK;

        // S(16x64) = Q @ K^T
        {
            wmma::fragment<wmma::accumulator, 16, 16, 8, float> sacc[4];
            #pragma unroll
            for (int j = 0; j < 4; j++) wmma::fill_fragment(sacc[j], 0.f);
            #pragma unroll
            for (int kk = 0; kk < 64; kk += 8) {
                wmma::fragment<wmma::matrix_a, 16, 16, 8, wmma::precision::tf32, wmma::row_major> af;
                wmma::load_matrix_sync(af, Qsh + r0 * ALD + kk, ALD);
                #pragma unroll
                for (int j = 0; j < 4; j++) {
                    wmma::fragment<wmma::matrix_b, 16, 16, 8, wmma::precision::tf32, wmma::col_major> bf;
                    wmma::load_matrix_sync(bf, Ks + (j * 16) * ALD + kk, ALD);
                    wmma::mma_sync(sacc[j], af, bf, sacc[j]);
                }
            }
            #pragma unroll
            for (int j = 0; j < 4; j++)
                wmma::store_matrix_sync(Ssh + r0 * ALD + j * 16, sacc[j], ALD, wmma::mem_row_major);
        }
        __syncwarp();

        // softmax numerator; round P to tf32 (feeds PV mma raw)
        {
            float* srow = Ssh + myrow * ALD + half * 32;
            int kbase = k0 + half * 32;
            float lsum = 0.f;
            #pragma unroll
            for (int c = 0; c < 32; c++) {
                float sv = srow[c] * 0.125f;
                float p = (kbase + c <= qi) ? __expf(fminf(sv, 60.f)) : 0.f;
                p = wmma::__float_to_tf32(p);
                srow[c] = p;
                lsum += p;
            }
            lacc += lsum;
        }
        __syncwarp();

        // O += P @ V
        #pragma unroll
        for (int kk = 0; kk < 64; kk += 8) {
            wmma::fragment<wmma::matrix_a, 16, 16, 8, wmma::precision::tf32, wmma::row_major> af;
            wmma::load_matrix_sync(af, Ssh + r0 * ALD + kk, ALD);
            #pragma unroll
            for (int j = 0; j < 4; j++) {
                wmma::fragment<wmma::matrix_b, 16, 16, 8, wmma::precision::tf32, wmma::row_major> bf;
                wmma::load_matrix_sync(bf, Vs + kk * ALD + j * 16, ALD);
                wmma::mma_sync(oacc[j], af, bf, oacc[j]);
            }
        }
    }

    lacc += __shfl_xor_sync(0xffffffff, lacc, 1);
    if (half == 0) rowl[myrow] = lacc;
    __syncwarp();

    #pragma unroll
    for (int j = 0; j < 4; j++)
        wmma::store_matrix_sync(Ssh + r0 * ALD + j * 16, oacc[j], ALD, wmma::mem_row_major);
    __syncwarp();

    #pragma unroll
    for (int i = 0; i < 8; i++) {
        int idx = lane + i * 32;
        int rr = r0 + (idx >> 4), cc = (idx & 15) * 4;
        float inv = 1.0f / rowl[rr];
        float4 v = *(float4*)(Ssh + rr * ALD + cc);
        v.x = wmma::__float_to_tf32(v.x * inv);
        v.y = wmma::__float_to_tf32(v.y * inv);
        v.z = wmma::__float_to_tf32(v.z * inv);
        v.w = wmma::__float_to_tf32(v.w * inv);
        *(float4*)(g_ao + (size_t)(b * T_SZ + q0 + rr) * C_SZ + h * D_SZ + cc) = v;
    }
}

// ---------------- launch ----------------
extern "C" void kernel_launch(void* const* d_in, const int* in_sizes, int n_in,
                              void* d_out, int out_size)
{
    const float* x    = (const float*)d_in[0];
    const float* Wqkv = (const float*)d_in[1];
    const float* bqkv = (const float*)d_in[2];
    const float* Wout = (const float*)d_in[3];
    const float* bout = (const float*)d_in[4];
    float* out = (float*)d_out;

    cudaFuncSetAttribute(gemm_tf32,
                         cudaFuncAttributeMaxDynamicSharedMemorySize, GEMM_SMEM_BYTES);
    cudaFuncSetAttribute(attn_kernel,
                         cudaFuncAttributeMaxDynamicSharedMemorySize, ATT_SMEM_BYTES);

    static float *p_xr = nullptr, *p_wqkv = nullptr, *p_wout = nullptr;
    if (!p_xr) {
        cudaGetSymbolAddress((void**)&p_xr,   g_xr);
        cudaGetSymbolAddress((void**)&p_wqkv, g_wqkv);
        cudaGetSymbolAddress((void**)&p_wout, g_wout);
    }

    // prep: round operands to tf32 once
    round_copy<<<(M_SZ * C_SZ / 4 + 255) / 256, 256>>>(x, p_xr, M_SZ * C_SZ / 4);
    round_copy<<<(3 * C_SZ * C_SZ / 4 + 255) / 256, 256>>>(Wqkv, p_wqkv, 3 * C_SZ * C_SZ / 4);
    round_copy<<<(C_SZ * C_SZ / 4 + 255) / 256, 256>>>(Wout, p_wout, C_SZ * C_SZ / 4);

    // 1) QKV projection
    dim3 g1(3 * C_SZ / BN, M_SZ / BM);   // (24, 32)
    gemm_tf32<<<g1, 256, GEMM_SMEM_BYTES>>>(bqkv, nullptr, M_SZ, 3 * C_SZ, C_SZ, 0);

    // 2) causal flash attention
    dim3 g2(T_SZ / AQ, B_SZ * H_SZ);     // (16, 64)
    attn_kernel<<<g2, 256, ATT_SMEM_BYTES>>>();

    // 3) output projection
    dim3 g3(C_SZ / BN, M_SZ / BM);       // (8, 32)
    gemm_tf32<<<g3, 256, GEMM_SMEM_BYTES>>>(bout, out, M_SZ, C_SZ, C_SZ, 1);
}

// round 8
// speedup vs baseline: 1.0561x; 1.0561x over previous
#include <cuda_runtime.h>
#include <mma.h>
#include <math.h>
#include <stdint.h>

using namespace nvcuda;

#define B_SZ 4
#define T_SZ 2048
#define C_SZ 1024
#define H_SZ 16
#define D_SZ 64
#define M_SZ (B_SZ * T_SZ)   // 8192

// ---------------- scratch (static device globals; no allocation) ----------------
__device__ float g_q[(size_t)B_SZ * H_SZ * T_SZ * D_SZ];   // [B,H,T,D] tf32-rounded
__device__ float g_k[(size_t)B_SZ * H_SZ * T_SZ * D_SZ];
__device__ float g_v[(size_t)B_SZ * H_SZ * T_SZ * D_SZ];
__device__ float g_ao[(size_t)B_SZ * T_SZ * C_SZ];         // attention out, tf32-rounded
__device__ float g_xr[(size_t)M_SZ * C_SZ];                // x, tf32-rounded
__device__ float g_wqkv[(size_t)C_SZ * 3 * C_SZ];          // W_qkv, tf32-rounded
__device__ float g_wout[(size_t)C_SZ * C_SZ];              // W_out, tf32-rounded

// ---------------- cp.async helpers ----------------
__device__ __forceinline__ void cp_async16(void* smem, const void* gmem) {
    uint32_t s = (uint32_t)__cvta_generic_to_shared(smem);
    asm volatile("cp.async.cg.shared.global [%0], [%1], 16;\n" :: "r"(s), "l"(gmem));
}
__device__ __forceinline__ void cp_commit() {
    asm volatile("cp.async.commit_group;\n");
}
template<int N>
__device__ __forceinline__ void cp_wait() {
    asm volatile("cp.async.wait_group %0;\n" :: "n"(N));
}

// ---------------- prep: round to tf32 in gmem ----------------
__global__ void round_copy(const float* __restrict__ src, float* __restrict__ dst, int n4) {
    int i = blockIdx.x * blockDim.x + threadIdx.x;
    if (i < n4) {
        float4 v = ((const float4*)src)[i];
        v.x = wmma::__float_to_tf32(v.x);
        v.y = wmma::__float_to_tf32(v.y);
        v.z = wmma::__float_to_tf32(v.z);
        v.w = wmma::__float_to_tf32(v.w);
        ((float4*)dst)[i] = v;
    }
}

// ---------------- GEMM v2: 256x128 CTA, 64x64 warp tiles, 3-stage ring ----------
// (unchanged from R6 — 713us known-good)
#define BM 256
#define BN 128
#define BK 32
#define GS 3
#define LDA (BK + 4)    // 36
#define LDB (BN + 4)    // 132
#define A_STG (BM * LDA)          // 9216 floats
#define B_STG (BK * LDB)          // 4224 floats
#define GEMM_SMEM_BYTES (GS * (A_STG + B_STG) * 4)   // 161280 B

__global__ void __launch_bounds__(256, 1) gemm_tf32(
    const float* __restrict__ bias, float* __restrict__ Cout,
    int M, int N, int K, int mode)
{
    extern __shared__ float gsm[];
    float* Ash = gsm;
    float* Bsh = gsm + GS * A_STG;

    const float* Aptr = (mode == 1) ? g_ao : g_xr;
    const float* Bm   = (mode == 1) ? g_wout : g_wqkv;

    int tid  = threadIdx.x;
    int warp = tid >> 5;
    int lane = tid & 31;
    int wm = warp >> 1;
    int wn = warp & 1;
    int m0 = blockIdx.y * BM;
    int n0 = blockIdx.x * BN;

    wmma::fragment<wmma::accumulator, 16, 16, 8, float> acc[4][4];
    #pragma unroll
    for (int i = 0; i < 4; i++)
        #pragma unroll
        for (int j = 0; j < 4; j++)
            wmma::fill_fragment(acc[i][j], 0.0f);

    int ar = tid >> 3,  ac = (tid & 7)  * 4;
    int br = tid >> 5,  bc = (tid & 31) * 4;

    auto load_tile = [&](int stage, int k0) {
        float* As = Ash + stage * A_STG;
        float* Bs = Bsh + stage * B_STG;
        #pragma unroll
        for (int i = 0; i < 8; i++) {
            int r = ar + i * 32;
            cp_async16(As + r * LDA + ac, Aptr + (size_t)(m0 + r) * K + k0 + ac);
        }
        #pragma unroll
        for (int i = 0; i < 4; i++) {
            int r = br + i * 8;
            cp_async16(Bs + r * LDB + bc, Bm + (size_t)(k0 + r) * N + n0 + bc);
        }
        cp_commit();
    };

    int KT = K / BK;
    load_tile(0, 0);
    load_tile(1, BK);

    for (int kt = 0; kt < KT; ++kt) {
        cp_wait<1>();
        __syncthreads();
        if (kt + 2 < KT) load_tile((kt + 2) % GS, (kt + 2) * BK);
        else             cp_commit();

        float* As = Ash + (kt % GS) * A_STG;
        float* Bs = Bsh + (kt % GS) * B_STG;

        #pragma unroll
        for (int kk = 0; kk < BK; kk += 8) {
            wmma::fragment<wmma::matrix_a, 16, 16, 8, wmma::precision::tf32, wmma::row_major> af[4];
            wmma::fragment<wmma::matrix_b, 16, 16, 8, wmma::precision::tf32, wmma::row_major> bf[4];
            #pragma unroll
            for (int i = 0; i < 4; i++)
                wmma::load_matrix_sync(af[i], As + (wm * 64 + i * 16) * LDA + kk, LDA);
            #pragma unroll
            for (int j = 0; j < 4; j++)
                wmma::load_matrix_sync(bf[j], Bs + kk * LDB + wn * 64 + j * 16, LDB);
            #pragma unroll
            for (int i = 0; i < 4; i++)
                #pragma unroll
                for (int j = 0; j < 4; j++)
                    wmma::mma_sync(acc[i][j], af[i], bf[j], acc[i][j]);
        }
    }
    __syncthreads();

    float* stg = Ash + warp * 256;
    #pragma unroll
    for (int i = 0; i < 4; i++) {
        #pragma unroll
        for (int j = 0; j < 4; j++) {
            wmma::store_matrix_sync(stg, acc[i][j], 16, wmma::mem_row_major);
            __syncwarp();
            #pragma unroll
            for (int e = 0; e < 8; e++) {
                int idx = lane + e * 32;
                int rr = idx >> 4, cc = idx & 15;
                int m = m0 + wm * 64 + i * 16 + rr;
                int n = n0 + wn * 64 + j * 16 + cc;
                float val = stg[idx] + bias[n];
                if (mode == 0) {
                    int third = n >> 10, c = n & 1023;
                    int h = c >> 6, d = c & 63;
                    int b = m >> 11, t = m & 2047;
                    float* dst = (third == 0) ? g_q : (third == 1) ? g_k : g_v;
                    dst[(((size_t)(b * H_SZ + h)) * T_SZ + t) * D_SZ + d] =
                        wmma::__float_to_tf32(val);
                } else {
                    Cout[(size_t)m * N + n] = val;
                }
            }
            __syncwarp();
        }
    }
}

// ---------------- Flash attention (causal), tf32 wmma, register K/V prefetch ------
// One CTA per (b,h,128-row Q tile). 8 warps, each owns 16 rows end-to-end.
// Single K/V smem buffer (2 CTAs/SM); next tile prefetched into registers
// while current tile computes.
#define AQ 128
#define AK 64
#define ALD 68
#define ATT_SMEM_FLOATS (AQ * ALD + AK * ALD + AK * ALD + AQ * ALD + AQ)
#define ATT_SMEM_BYTES  (ATT_SMEM_FLOATS * 4)   // 104960 B -> 2 CTAs/SM

__global__ void __launch_bounds__(256, 2) attn_kernel()
{
    extern __shared__ float smbuf[];
    float* Qsh  = smbuf;
    float* Ksh  = Qsh + AQ * ALD;
    float* Vsh  = Ksh + AK * ALD;
    float* Ssh  = Vsh + AK * ALD;
    float* rowl = Ssh + AQ * ALD;

    int qt = gridDim.x - 1 - blockIdx.x;   // longest tiles first
    int q0 = qt * AQ;
    int bh = blockIdx.y;
    int b = bh >> 4, h = bh & 15;

    const float* Qb = g_q + (size_t)bh * T_SZ * D_SZ;
    const float* Kb = g_k + (size_t)bh * T_SZ * D_SZ;
    const float* Vb = g_v + (size_t)bh * T_SZ * D_SZ;

    int tid  = threadIdx.x;
    int warp = tid >> 5;
    int lane = tid & 31;
    int r0 = warp * 16;

    // load Q tile
    #pragma unroll
    for (int i = 0; i < 8; i++) {
        int idx = tid + i * 256;
        int r = idx >> 4, c = (idx & 15) * 4;
        *(float4*)(Qsh + r * ALD + c) = *(const float4*)(Qb + (size_t)(q0 + r) * D_SZ + c);
    }

    // register prefetch buffers: this thread's slice of one K tile + one V tile
    int kr = tid >> 4, kc = (tid & 15) * 4;   // 4 rows each (stride 16)
    float4 kbuf[4], vbuf[4];
    auto ldg_kv = [&](int k0) {
        #pragma unroll
        for (int i = 0; i < 4; i++) {
            int r = k0 + kr + i * 16;
            kbuf[i] = *(const float4*)(Kb + (size_t)r * D_SZ + kc);
            vbuf[i] = *(const float4*)(Vb + (size_t)r * D_SZ + kc);
        }
    };
    auto sts_kv = [&]() {
        #pragma unroll
        for (int i = 0; i < 4; i++) {
            int r = kr + i * 16;
            *(float4*)(Ksh + r * ALD + kc) = kbuf[i];
            *(float4*)(Vsh + r * ALD + kc) = vbuf[i];
        }
    };

    wmma::fragment<wmma::accumulator, 16, 16, 8, float> oacc[4];
    #pragma unroll
    for (int j = 0; j < 4; j++) wmma::fill_fragment(oacc[j], 0.f);

    float lacc = 0.f;
    int rl = lane >> 1, half = lane & 1;
    int myrow = r0 + rl;
    int qi = q0 + myrow;

    int nkt = 2 * qt + 2;
    ldg_kv(0);                           // prefetch tile 0 (overlaps Q load)

    for (int kt = 0; kt < nkt; ++kt) {
        int k0 = kt * AK;
        __syncthreads();                 // all warps done reading prev K/V smem
        sts_kv();                        // publish tile kt from regs
        if (kt + 1 < nkt) ldg_kv(k0 + AK);   // LDGs fly under the compute below
        __syncthreads();                 // tile kt visible

        // S(16x64) = Q @ K^T
        {
            wmma::fragment<wmma::accumulator, 16, 16, 8, float> sacc[4];
            #pragma unroll
            for (int j = 0; j < 4; j++) wmma::fill_fragment(sacc[j], 0.f);
            #pragma unroll
            for (int kk = 0; kk < 64; kk += 8) {
                wmma::fragment<wmma::matrix_a, 16, 16, 8, wmma::precision::tf32, wmma::row_major> af;
                wmma::load_matrix_sync(af, Qsh + r0 * ALD + kk, ALD);
                #pragma unroll
                for (int j = 0; j < 4; j++) {
                    wmma::fragment<wmma::matrix_b, 16, 16, 8, wmma::precision::tf32, wmma::col_major> bf;
                    wmma::load_matrix_sync(bf, Ksh + (j * 16) * ALD + kk, ALD);
                    wmma::mma_sync(sacc[j], af, bf, sacc[j]);
                }
            }
            #pragma unroll
            for (int j = 0; j < 4; j++)
                wmma::store_matrix_sync(Ssh + r0 * ALD + j * 16, sacc[j], ALD, wmma::mem_row_major);
        }
        __syncwarp();

        // softmax numerator; round P to tf32 (feeds PV mma raw)
        {
            float* srow = Ssh + myrow * ALD + half * 32;
            int kbase = k0 + half * 32;
            float lsum = 0.f;
            #pragma unroll
            for (int c = 0; c < 32; c++) {
                float sv = srow[c] * 0.125f;
                float p = (kbase + c <= qi) ? __expf(fminf(sv, 60.f)) : 0.f;
                p = wmma::__float_to_tf32(p);
                srow[c] = p;
                lsum += p;
            }
            lacc += lsum;
        }
        __syncwarp();

        // O += P @ V
        #pragma unroll
        for (int kk = 0; kk < 64; kk += 8) {
            wmma::fragment<wmma::matrix_a, 16, 16, 8, wmma::precision::tf32, wmma::row_major> af;
            wmma::load_matrix_sync(af, Ssh + r0 * ALD + kk, ALD);
            #pragma unroll
            for (int j = 0; j < 4; j++) {
                wmma::fragment<wmma::matrix_b, 16, 16, 8, wmma::precision::tf32, wmma::row_major> bf;
                wmma::load_matrix_sync(bf, Vsh + kk * ALD + j * 16, ALD);
                wmma::mma_sync(oacc[j], af, bf, oacc[j]);
            }
        }
    }

    lacc += __shfl_xor_sync(0xffffffff, lacc, 1);
    if (half == 0) rowl[myrow] = lacc;
    __syncwarp();

    #pragma unroll
    for (int j = 0; j < 4; j++)
        wmma::store_matrix_sync(Ssh + r0 * ALD + j * 16, oacc[j], ALD, wmma::mem_row_major);
    __syncwarp();

    #pragma unroll
    for (int i = 0; i < 8; i++) {
        int idx = lane + i * 32;
        int rr = r0 + (idx >> 4), cc = (idx & 15) * 4;
        float inv = 1.0f / rowl[rr];
        float4 v = *(float4*)(Ssh + rr * ALD + cc);
        v.x = wmma::__float_to_tf32(v.x * inv);
        v.y = wmma::__float_to_tf32(v.y * inv);
        v.z = wmma::__float_to_tf32(v.z * inv);
        v.w = wmma::__float_to_tf32(v.w * inv);
        *(float4*)(g_ao + (size_t)(b * T_SZ + q0 + rr) * C_SZ + h * D_SZ + cc) = v;
    }
}

// ---------------- launch ----------------
extern "C" void kernel_launch(void* const* d_in, const int* in_sizes, int n_in,
                              void* d_out, int out_size)
{
    const float* x    = (const float*)d_in[0];
    const float* Wqkv = (const float*)d_in[1];
    const float* bqkv = (const float*)d_in[2];
    const float* Wout = (const float*)d_in[3];
    const float* bout = (const float*)d_in[4];
    float* out = (float*)d_out;

    cudaFuncSetAttribute(gemm_tf32,
                         cudaFuncAttributeMaxDynamicSharedMemorySize, GEMM_SMEM_BYTES);
    cudaFuncSetAttribute(attn_kernel,
                         cudaFuncAttributeMaxDynamicSharedMemorySize, ATT_SMEM_BYTES);

    static float *p_xr = nullptr, *p_wqkv = nullptr, *p_wout = nullptr;
    if (!p_xr) {
        cudaGetSymbolAddress((void**)&p_xr,   g_xr);
        cudaGetSymbolAddress((void**)&p_wqkv, g_wqkv);
        cudaGetSymbolAddress((void**)&p_wout, g_wout);
    }

    // prep: round operands to tf32 once
    round_copy<<<(M_SZ * C_SZ / 4 + 255) / 256, 256>>>(x, p_xr, M_SZ * C_SZ / 4);
    round_copy<<<(3 * C_SZ * C_SZ / 4 + 255) / 256, 256>>>(Wqkv, p_wqkv, 3 * C_SZ * C_SZ / 4);
    round_copy<<<(C_SZ * C_SZ / 4 + 255) / 256, 256>>>(Wout, p_wout, C_SZ * C_SZ / 4);

    // 1) QKV projection
    dim3 g1(3 * C_SZ / BN, M_SZ / BM);   // (24, 32)
    gemm_tf32<<<g1, 256, GEMM_SMEM_BYTES>>>(bqkv, nullptr, M_SZ, 3 * C_SZ, C_SZ, 0);

    // 2) causal flash attention
    dim3 g2(T_SZ / AQ, B_SZ * H_SZ);     // (16, 64)
    attn_kernel<<<g2, 256, ATT_SMEM_BYTES>>>();

    // 3) output projection
    dim3 g3(C_SZ / BN, M_SZ / BM);       // (8, 32)
    gemm_tf32<<<g3, 256, GEMM_SMEM_BYTES>>>(bout, out, M_SZ, C_SZ, C_SZ, 1);
}

// round 9
// speedup vs baseline: 1.0878x; 1.0300x over previous
#include <cuda_runtime.h>
#include <mma.h>
#include <math.h>
#include <stdint.h>

using namespace nvcuda;

#define B_SZ 4
#define T_SZ 2048
#define C_SZ 1024
#define H_SZ 16
#define D_SZ 64
#define M_SZ (B_SZ * T_SZ)   // 8192

// ---------------- scratch (static device globals; no allocation) ----------------
__device__ float g_q[(size_t)B_SZ * H_SZ * T_SZ * D_SZ];   // [B,H,T,D] tf32-rounded
__device__ float g_k[(size_t)B_SZ * H_SZ * T_SZ * D_SZ];
__device__ float g_v[(size_t)B_SZ * H_SZ * T_SZ * D_SZ];
__device__ float g_ao[(size_t)B_SZ * T_SZ * C_SZ];         // attention out, tf32-rounded
__device__ float g_xr[(size_t)M_SZ * C_SZ];                // x, tf32-rounded
__device__ float g_wqkv[(size_t)C_SZ * 3 * C_SZ];          // W_qkv, tf32-rounded
__device__ float g_wout[(size_t)C_SZ * C_SZ];              // W_out, tf32-rounded

// ---------------- cp.async helpers ----------------
__device__ __forceinline__ void cp_async16(void* smem, const void* gmem) {
    uint32_t s = (uint32_t)__cvta_generic_to_shared(smem);
    asm volatile("cp.async.cg.shared.global [%0], [%1], 16;\n" :: "r"(s), "l"(gmem));
}
__device__ __forceinline__ void cp_commit() {
    asm volatile("cp.async.commit_group;\n");
}
template<int N>
__device__ __forceinline__ void cp_wait() {
    asm volatile("cp.async.wait_group %0;\n" :: "n"(N));
}

// ---------------- prep: round to tf32 in gmem ----------------
__global__ void round_copy(const float* __restrict__ src, float* __restrict__ dst, int n4) {
    int i = blockIdx.x * blockDim.x + threadIdx.x;
    if (i < n4) {
        float4 v = ((const float4*)src)[i];
        v.x = wmma::__float_to_tf32(v.x);
        v.y = wmma::__float_to_tf32(v.y);
        v.z = wmma::__float_to_tf32(v.z);
        v.w = wmma::__float_to_tf32(v.w);
        ((float4*)dst)[i] = v;
    }
}

// ---------------- GEMM v2: 256x128 CTA, 64x64 warp tiles, 3-stage ring ----------
#define BM 256
#define BN 128
#define BK 32
#define GS 3
#define LDA (BK + 4)    // 36
#define LDB (BN + 4)    // 132
#define A_STG (BM * LDA)          // 9216 floats
#define B_STG (BK * LDB)          // 4224 floats
#define GEMM_SMEM_BYTES (GS * (A_STG + B_STG) * 4)   // 161280 B

__global__ void __launch_bounds__(256, 1) gemm_tf32(
    const float* __restrict__ bias, float* __restrict__ Cout,
    int M, int N, int K, int mode)
{
    extern __shared__ float gsm[];
    float* Ash = gsm;
    float* Bsh = gsm + GS * A_STG;

    const float* Aptr = (mode == 1) ? g_ao : g_xr;
    const float* Bm   = (mode == 1) ? g_wout : g_wqkv;

    int tid  = threadIdx.x;
    int warp = tid >> 5;
    int lane = tid & 31;
    int wm = warp >> 1;
    int wn = warp & 1;
    int m0 = blockIdx.y * BM;
    int n0 = blockIdx.x * BN;

    wmma::fragment<wmma::accumulator, 16, 16, 8, float> acc[4][4];
    #pragma unroll
    for (int i = 0; i < 4; i++)
        #pragma unroll
        for (int j = 0; j < 4; j++)
            wmma::fill_fragment(acc[i][j], 0.0f);

    int ar = tid >> 3,  ac = (tid & 7)  * 4;
    int br = tid >> 5,  bc = (tid & 31) * 4;

    auto load_tile = [&](int stage, int k0) {
        float* As = Ash + stage * A_STG;
        float* Bs = Bsh + stage * B_STG;
        #pragma unroll
        for (int i = 0; i < 8; i++) {
            int r = ar + i * 32;
            cp_async16(As + r * LDA + ac, Aptr + (size_t)(m0 + r) * K + k0 + ac);
        }
        #pragma unroll
        for (int i = 0; i < 4; i++) {
            int r = br + i * 8;
            cp_async16(Bs + r * LDB + bc, Bm + (size_t)(k0 + r) * N + n0 + bc);
        }
        cp_commit();
    };

    int KT = K / BK;
    load_tile(0, 0);
    load_tile(1, BK);

    for (int kt = 0; kt < KT; ++kt) {
        cp_wait<1>();
        __syncthreads();
        if (kt + 2 < KT) load_tile((kt + 2) % GS, (kt + 2) * BK);
        else             cp_commit();

        float* As = Ash + (kt % GS) * A_STG;
        float* Bs = Bsh + (kt % GS) * B_STG;

        #pragma unroll
        for (int kk = 0; kk < BK; kk += 8) {
            wmma::fragment<wmma::matrix_a, 16, 16, 8, wmma::precision::tf32, wmma::row_major> af[4];
            wmma::fragment<wmma::matrix_b, 16, 16, 8, wmma::precision::tf32, wmma::row_major> bf[4];
            #pragma unroll
            for (int i = 0; i < 4; i++)
                wmma::load_matrix_sync(af[i], As + (wm * 64 + i * 16) * LDA + kk, LDA);
            #pragma unroll
            for (int j = 0; j < 4; j++)
                wmma::load_matrix_sync(bf[j], Bs + kk * LDB + wn * 64 + j * 16, LDB);
            #pragma unroll
            for (int i = 0; i < 4; i++)
                #pragma unroll
                for (int j = 0; j < 4; j++)
                    wmma::mma_sync(acc[i][j], af[i], bf[j], acc[i][j]);
        }
    }
    __syncthreads();

    // Epilogue (vectorized): each lane handles half a fragment row as 2 float4s.
    float* stg = Ash + warp * 256;
    int err = lane >> 1;            // 0..15 (fragment row)
    int ecc = (lane & 1) * 8;       // 0 or 8 (col base)
    #pragma unroll
    for (int i = 0; i < 4; i++) {
        #pragma unroll
        for (int j = 0; j < 4; j++) {
            wmma::store_matrix_sync(stg, acc[i][j], 16, wmma::mem_row_major);
            __syncwarp();
            int m = m0 + wm * 64 + i * 16 + err;
            int nb = n0 + wn * 64 + j * 16 + ecc;
            #pragma unroll
            for (int e = 0; e < 2; e++) {
                int n = nb + e * 4;
                float4 v  = *(float4*)(stg + err * 16 + ecc + e * 4);
                float4 bv = *(const float4*)(bias + n);
                v.x += bv.x; v.y += bv.y; v.z += bv.z; v.w += bv.w;
                if (mode == 0) {
                    int third = n >> 10, c = n & 1023;
                    int h = c >> 6, d = c & 63;
                    int b = m >> 11, t = m & 2047;
                    float* dst = (third == 0) ? g_q : (third == 1) ? g_k : g_v;
                    v.x = wmma::__float_to_tf32(v.x);
                    v.y = wmma::__float_to_tf32(v.y);
                    v.z = wmma::__float_to_tf32(v.z);
                    v.w = wmma::__float_to_tf32(v.w);
                    *(float4*)(dst + (((size_t)(b * H_SZ + h)) * T_SZ + t) * D_SZ + d) = v;
                } else {
                    *(float4*)(Cout + (size_t)m * N + n) = v;
                }
            }
            __syncwarp();
        }
    }
}

// ---------------- Flash attention (causal), tf32 wmma, register K/V prefetch ------
// Scale 1/sqrt(D)=0.125 folded into Q at load (power of 2 -> tf32-exact).
#define AQ 128
#define AK 64
#define ALD 68
#define ATT_SMEM_FLOATS (AQ * ALD + AK * ALD + AK * ALD + AQ * ALD + AQ)
#define ATT_SMEM_BYTES  (ATT_SMEM_FLOATS * 4)   // 104960 B -> 2 CTAs/SM

__global__ void __launch_bounds__(256, 2) attn_kernel()
{
    extern __shared__ float smbuf[];
    float* Qsh  = smbuf;
    float* Ksh  = Qsh + AQ * ALD;
    float* Vsh  = Ksh + AK * ALD;
    float* Ssh  = Vsh + AK * ALD;
    float* rowl = Ssh + AQ * ALD;

    int qt = gridDim.x - 1 - blockIdx.x;   // longest tiles first
    int q0 = qt * AQ;
    int bh = blockIdx.y;
    int b = bh >> 4, h = bh & 15;

    const float* Qb = g_q + (size_t)bh * T_SZ * D_SZ;
    const float* Kb = g_k + (size_t)bh * T_SZ * D_SZ;
    const float* Vb = g_v + (size_t)bh * T_SZ * D_SZ;

    int tid  = threadIdx.x;
    int warp = tid >> 5;
    int lane = tid & 31;
    int r0 = warp * 16;

    // load Q tile with 0.125 scale folded in
    #pragma unroll
    for (int i = 0; i < 8; i++) {
        int idx = tid + i * 256;
        int r = idx >> 4, c = (idx & 15) * 4;
        float4 v = *(const float4*)(Qb + (size_t)(q0 + r) * D_SZ + c);
        v.x *= 0.125f; v.y *= 0.125f; v.z *= 0.125f; v.w *= 0.125f;
        *(float4*)(Qsh + r * ALD + c) = v;
    }

    // register prefetch buffers: this thread's slice of one K tile + one V tile
    int kr = tid >> 4, kc = (tid & 15) * 4;
    float4 kbuf[4], vbuf[4];
    auto ldg_kv = [&](int k0) {
        #pragma unroll
        for (int i = 0; i < 4; i++) {
            int r = k0 + kr + i * 16;
            kbuf[i] = *(const float4*)(Kb + (size_t)r * D_SZ + kc);
            vbuf[i] = *(const float4*)(Vb + (size_t)r * D_SZ + kc);
        }
    };
    auto sts_kv = [&]() {
        #pragma unroll
        for (int i = 0; i < 4; i++) {
            int r = kr + i * 16;
            *(float4*)(Ksh + r * ALD + kc) = kbuf[i];
            *(float4*)(Vsh + r * ALD + kc) = vbuf[i];
        }
    };

    wmma::fragment<wmma::accumulator, 16, 16, 8, float> oacc[4];
    #pragma unroll
    for (int j = 0; j < 4; j++) wmma::fill_fragment(oacc[j], 0.f);

    float lacc = 0.f;
    int rl = lane >> 1, half = lane & 1;
    int myrow = r0 + rl;
    int qi = q0 + myrow;

    int nkt = 2 * qt + 2;
    ldg_kv(0);

    for (int kt = 0; kt < nkt; ++kt) {
        int k0 = kt * AK;
        __syncthreads();
        sts_kv();
        if (kt + 1 < nkt) ldg_kv(k0 + AK);
        __syncthreads();

        // S(16x64) = (Q*0.125) @ K^T
        {
            wmma::fragment<wmma::accumulator, 16, 16, 8, float> sacc[4];
            #pragma unroll
            for (int j = 0; j < 4; j++) wmma::fill_fragment(sacc[j], 0.f);
            #pragma unroll
            for (int kk = 0; kk < 64; kk += 8) {
                wmma::fragment<wmma::matrix_a, 16, 16, 8, wmma::precision::tf32, wmma::row_major> af;
                wmma::load_matrix_sync(af, Qsh + r0 * ALD + kk, ALD);
                #pragma unroll
                for (int j = 0; j < 4; j++) {
                    wmma::fragment<wmma::matrix_b, 16, 16, 8, wmma::precision::tf32, wmma::col_major> bf;
                    wmma::load_matrix_sync(bf, Ksh + (j * 16) * ALD + kk, ALD);
                    wmma::mma_sync(sacc[j], af, bf, sacc[j]);
                }
            }
            #pragma unroll
            for (int j = 0; j < 4; j++)
                wmma::store_matrix_sync(Ssh + r0 * ALD + j * 16, sacc[j], ALD, wmma::mem_row_major);
        }
        __syncwarp();

        // softmax numerator (vectorized float4); round P to tf32 for the PV mma
        {
            float* srow = Ssh + myrow * ALD + half * 32;
            int kbase = k0 + half * 32;
            float lsum = 0.f;
            #pragma unroll
            for (int c4 = 0; c4 < 8; c4++) {
                float4 sv = *(float4*)(srow + c4 * 4);
                int cb = kbase + c4 * 4;
                float p0 = (cb + 0 <= qi) ? __expf(fminf(sv.x, 60.f)) : 0.f;
                float p1 = (cb + 1 <= qi) ? __expf(fminf(sv.y, 60.f)) : 0.f;
                float p2 = (cb + 2 <= qi) ? __expf(fminf(sv.z, 60.f)) : 0.f;
                float p3 = (cb + 3 <= qi) ? __expf(fminf(sv.w, 60.f)) : 0.f;
                p0 = wmma::__float_to_tf32(p0);
                p1 = wmma::__float_to_tf32(p1);
                p2 = wmma::__float_to_tf32(p2);
                p3 = wmma::__float_to_tf32(p3);
                float4 pv = make_float4(p0, p1, p2, p3);
                *(float4*)(srow + c4 * 4) = pv;
                lsum += (p0 + p1) + (p2 + p3);
            }
            lacc += lsum;
        }
        __syncwarp();

        // O += P @ V
        #pragma unroll
        for (int kk = 0; kk < 64; kk += 8) {
            wmma::fragment<wmma::matrix_a, 16, 16, 8, wmma::precision::tf32, wmma::row_major> af;
            wmma::load_matrix_sync(af, Ssh + r0 * ALD + kk, ALD);
            #pragma unroll
            for (int j = 0; j < 4; j++) {
                wmma::fragment<wmma::matrix_b, 16, 16, 8, wmma::precision::tf32, wmma::row_major> bf;
                wmma::load_matrix_sync(bf, Vsh + kk * ALD + j * 16, ALD);
                wmma::mma_sync(oacc[j], af, bf, oacc[j]);
            }
        }
    }

    lacc += __shfl_xor_sync(0xffffffff, lacc, 1);
    if (half == 0) rowl[myrow] = lacc;
    __syncwarp();

    #pragma unroll
    for (int j = 0; j < 4; j++)
        wmma::store_matrix_sync(Ssh + r0 * ALD + j * 16, oacc[j], ALD, wmma::mem_row_major);
    __syncwarp();

    #pragma unroll
    for (int i = 0; i < 8; i++) {
        int idx = lane + i * 32;
        int rr = r0 + (idx >> 4), cc = (idx & 15) * 4;
        float inv = 1.0f / rowl[rr];
        float4 v = *(float4*)(Ssh + rr * ALD + cc);
        v.x = wmma::__float_to_tf32(v.x * inv);
        v.y = wmma::__float_to_tf32(v.y * inv);
        v.z = wmma::__float_to_tf32(v.z * inv);
        v.w = wmma::__float_to_tf32(v.w * inv);
        *(float4*)(g_ao + (size_t)(b * T_SZ + q0 + rr) * C_SZ + h * D_SZ + cc) = v;
    }
}

// ---------------- launch ----------------
extern "C" void kernel_launch(void* const* d_in, const int* in_sizes, int n_in,
                              void* d_out, int out_size)
{
    const float* x    = (const float*)d_in[0];
    const float* Wqkv = (const float*)d_in[1];
    const float* bqkv = (const float*)d_in[2];
    const float* Wout = (const float*)d_in[3];
    const float* bout = (const float*)d_in[4];
    float* out = (float*)d_out;

    cudaFuncSetAttribute(gemm_tf32,
                         cudaFuncAttributeMaxDynamicSharedMemorySize, GEMM_SMEM_BYTES);
    cudaFuncSetAttribute(attn_kernel,
                         cudaFuncAttributeMaxDynamicSharedMemorySize, ATT_SMEM_BYTES);

    static float *p_xr = nullptr, *p_wqkv = nullptr, *p_wout = nullptr;
    if (!p_xr) {
        cudaGetSymbolAddress((void**)&p_xr,   g_xr);
        cudaGetSymbolAddress((void**)&p_wqkv, g_wqkv);
        cudaGetSymbolAddress((void**)&p_wout, g_wout);
    }

    // prep: round operands to tf32 once
    round_copy<<<(M_SZ * C_SZ / 4 + 255) / 256, 256>>>(x, p_xr, M_SZ * C_SZ / 4);
    round_copy<<<(3 * C_SZ * C_SZ / 4 + 255) / 256, 256>>>(Wqkv, p_wqkv, 3 * C_SZ * C_SZ / 4);
    round_copy<<<(C_SZ * C_SZ / 4 + 255) / 256, 256>>>(Wout, p_wout, C_SZ * C_SZ / 4);

    // 1) QKV projection
    dim3 g1(3 * C_SZ / BN, M_SZ / BM);   // (24, 32)
    gemm_tf32<<<g1, 256, GEMM_SMEM_BYTES>>>(bqkv, nullptr, M_SZ, 3 * C_SZ, C_SZ, 0);

    // 2) causal flash attention
    dim3 g2(T_SZ / AQ, B_SZ * H_SZ);     // (16, 64)
    attn_kernel<<<g2, 256, ATT_SMEM_BYTES>>>();

    // 3) output projection
    dim3 g3(C_SZ / BN, M_SZ / BM);       // (8, 32)
    gemm_tf32<<<g3, 256, GEMM_SMEM_BYTES>>>(bout, out, M_SZ, C_SZ, C_SZ, 1);
}

// round 10
// speedup vs baseline: 1.3932x; 1.2808x over previous
#include <cuda_runtime.h>
#include <mma.h>
#include <math.h>
#include <stdint.h>

using namespace nvcuda;

#define B_SZ 4
#define T_SZ 2048
#define C_SZ 1024
#define H_SZ 16
#define D_SZ 64
#define M_SZ (B_SZ * T_SZ)   // 8192

// ---------------- scratch (static device globals; no allocation) ----------------
__device__ float g_q[(size_t)B_SZ * H_SZ * T_SZ * D_SZ];   // [B,H,T,D] tf32-rounded
__device__ float g_k[(size_t)B_SZ * H_SZ * T_SZ * D_SZ];
__device__ float g_v[(size_t)B_SZ * H_SZ * T_SZ * D_SZ];
__device__ float g_ao[(size_t)B_SZ * T_SZ * C_SZ];         // attention out, tf32-rounded
__device__ float g_xr[(size_t)M_SZ * C_SZ];                // x, tf32-rounded
__device__ float g_wqkv[(size_t)C_SZ * 3 * C_SZ];          // W_qkv, tf32-rounded
__device__ float g_wout[(size_t)C_SZ * C_SZ];              // W_out, tf32-rounded

// ---------------- cp.async helpers ----------------
__device__ __forceinline__ void cp_async16(void* smem, const void* gmem) {
    uint32_t s = (uint32_t)__cvta_generic_to_shared(smem);
    asm volatile("cp.async.cg.shared.global [%0], [%1], 16;\n" :: "r"(s), "l"(gmem));
}
__device__ __forceinline__ void cp_commit() {
    asm volatile("cp.async.commit_group;\n");
}
template<int N>
__device__ __forceinline__ void cp_wait() {
    asm volatile("cp.async.wait_group %0;\n" :: "n"(N));
}

// ---------------- raw tf32 mma (PTX-defined fragment layout) ----------------
__device__ __forceinline__ void mma_tf32(float* c, const uint32_t* a, const uint32_t* b) {
    asm volatile(
        "mma.sync.aligned.m16n8k8.row.col.f32.tf32.tf32.f32 "
        "{%0,%1,%2,%3}, {%4,%5,%6,%7}, {%8,%9}, {%0,%1,%2,%3};\n"
        : "+f"(c[0]), "+f"(c[1]), "+f"(c[2]), "+f"(c[3])
        : "r"(a[0]), "r"(a[1]), "r"(a[2]), "r"(a[3]), "r"(b[0]), "r"(b[1]));
}

// ---------------- prep: round to tf32 in gmem ----------------
__global__ void round_copy(const float* __restrict__ src, float* __restrict__ dst, int n4) {
    int i = blockIdx.x * blockDim.x + threadIdx.x;
    if (i < n4) {
        float4 v = ((const float4*)src)[i];
        v.x = wmma::__float_to_tf32(v.x);
        v.y = wmma::__float_to_tf32(v.y);
        v.z = wmma::__float_to_tf32(v.z);
        v.w = wmma::__float_to_tf32(v.w);
        ((float4*)dst)[i] = v;
    }
}

// ---------------- GEMM v2: 256x128 CTA, 64x64 warp tiles, 3-stage ring ----------
// (unchanged — 713us known-good)
#define BM 256
#define BN 128
#define BK 32
#define GS 3
#define LDA (BK + 4)    // 36
#define LDB (BN + 4)    // 132
#define A_STG (BM * LDA)
#define B_STG (BK * LDB)
#define GEMM_SMEM_BYTES (GS * (A_STG + B_STG) * 4)   // 161280 B

__global__ void __launch_bounds__(256, 1) gemm_tf32(
    const float* __restrict__ bias, float* __restrict__ Cout,
    int M, int N, int K, int mode)
{
    extern __shared__ float gsm[];
    float* Ash = gsm;
    float* Bsh = gsm + GS * A_STG;

    const float* Aptr = (mode == 1) ? g_ao : g_xr;
    const float* Bm   = (mode == 1) ? g_wout : g_wqkv;

    int tid  = threadIdx.x;
    int warp = tid >> 5;
    int lane = tid & 31;
    int wm = warp >> 1;
    int wn = warp & 1;
    int m0 = blockIdx.y * BM;
    int n0 = blockIdx.x * BN;

    wmma::fragment<wmma::accumulator, 16, 16, 8, float> acc[4][4];
    #pragma unroll
    for (int i = 0; i < 4; i++)
        #pragma unroll
        for (int j = 0; j < 4; j++)
            wmma::fill_fragment(acc[i][j], 0.0f);

    int ar = tid >> 3,  ac = (tid & 7)  * 4;
    int br = tid >> 5,  bc = (tid & 31) * 4;

    auto load_tile = [&](int stage, int k0) {
        float* As = Ash + stage * A_STG;
        float* Bs = Bsh + stage * B_STG;
        #pragma unroll
        for (int i = 0; i < 8; i++) {
            int r = ar + i * 32;
            cp_async16(As + r * LDA + ac, Aptr + (size_t)(m0 + r) * K + k0 + ac);
        }
        #pragma unroll
        for (int i = 0; i < 4; i++) {
            int r = br + i * 8;
            cp_async16(Bs + r * LDB + bc, Bm + (size_t)(k0 + r) * N + n0 + bc);
        }
        cp_commit();
    };

    int KT = K / BK;
    load_tile(0, 0);
    load_tile(1, BK);

    for (int kt = 0; kt < KT; ++kt) {
        cp_wait<1>();
        __syncthreads();
        if (kt + 2 < KT) load_tile((kt + 2) % GS, (kt + 2) * BK);
        else             cp_commit();

        float* As = Ash + (kt % GS) * A_STG;
        float* Bs = Bsh + (kt % GS) * B_STG;

        #pragma unroll
        for (int kk = 0; kk < BK; kk += 8) {
            wmma::fragment<wmma::matrix_a, 16, 16, 8, wmma::precision::tf32, wmma::row_major> af[4];
            wmma::fragment<wmma::matrix_b, 16, 16, 8, wmma::precision::tf32, wmma::row_major> bf[4];
            #pragma unroll
            for (int i = 0; i < 4; i++)
                wmma::load_matrix_sync(af[i], As + (wm * 64 + i * 16) * LDA + kk, LDA);
            #pragma unroll
            for (int j = 0; j < 4; j++)
                wmma::load_matrix_sync(bf[j], Bs + kk * LDB + wn * 64 + j * 16, LDB);
            #pragma unroll
            for (int i = 0; i < 4; i++)
                #pragma unroll
                for (int j = 0; j < 4; j++)
                    wmma::mma_sync(acc[i][j], af[i], bf[j], acc[i][j]);
        }
    }
    __syncthreads();

    // Epilogue (vectorized)
    float* stg = Ash + warp * 256;
    int err = lane >> 1;
    int ecc = (lane & 1) * 8;
    #pragma unroll
    for (int i = 0; i < 4; i++) {
        #pragma unroll
        for (int j = 0; j < 4; j++) {
            wmma::store_matrix_sync(stg, acc[i][j], 16, wmma::mem_row_major);
            __syncwarp();
            int m = m0 + wm * 64 + i * 16 + err;
            int nb = n0 + wn * 64 + j * 16 + ecc;
            #pragma unroll
            for (int e = 0; e < 2; e++) {
                int n = nb + e * 4;
                float4 v  = *(float4*)(stg + err * 16 + ecc + e * 4);
                float4 bv = *(const float4*)(bias + n);
                v.x += bv.x; v.y += bv.y; v.z += bv.z; v.w += bv.w;
                if (mode == 0) {
                    int third = n >> 10, c = n & 1023;
                    int h = c >> 6, d = c & 63;
                    int b = m >> 11, t = m & 2047;
                    float* dst = (third == 0) ? g_q : (third == 1) ? g_k : g_v;
                    v.x = wmma::__float_to_tf32(v.x);
                    v.y = wmma::__float_to_tf32(v.y);
                    v.z = wmma::__float_to_tf32(v.z);
                    v.w = wmma::__float_to_tf32(v.w);
                    *(float4*)(dst + (((size_t)(b * H_SZ + h)) * T_SZ + t) * D_SZ + d) = v;
                } else {
                    *(float4*)(Cout + (size_t)m * N + n) = v;
                }
            }
            __syncwarp();
        }
    }
}

// ---------------- Flash attention, raw m16n8k8 mma, register softmax -------------
// One CTA per (b,h,128-row Q tile). 8 warps, each owns 16 rows end-to-end.
// S accumulator stays in registers through softmax; P goes to smem once for the
// PV A-operand. O normalized in registers. Scale 1/8 folded into Q.
#define AQ 128
#define AK 64
#define ALD 68
#define ATT_SMEM_FLOATS (AQ * ALD + AK * ALD + AK * ALD + AQ * ALD)
#define ATT_SMEM_BYTES  (ATT_SMEM_FLOATS * 4)   // 104448 B -> 2 CTAs/SM

__global__ void __launch_bounds__(256, 2) attn_kernel()
{
    extern __shared__ float smbuf[];
    float* Qsh = smbuf;
    float* Ksh = Qsh + AQ * ALD;
    float* Vsh = Ksh + AK * ALD;
    float* Ssh = Vsh + AK * ALD;

    int qt = gridDim.x - 1 - blockIdx.x;   // longest tiles first
    int q0 = qt * AQ;
    int bh = blockIdx.y;
    int b = bh >> 4, h = bh & 15;

    const float* Qb = g_q + (size_t)bh * T_SZ * D_SZ;
    const float* Kb = g_k + (size_t)bh * T_SZ * D_SZ;
    const float* Vb = g_v + (size_t)bh * T_SZ * D_SZ;

    int tid  = threadIdx.x;
    int warp = tid >> 5;
    int lane = tid & 31;
    int r0 = warp * 16;
    int g = lane >> 2;        // quad group: rows g, g+8 within warp band
    int t = lane & 3;         // lane within quad
    int rowA = r0 + g, rowB = rowA + 8;
    int qiA = q0 + rowA, qiB = q0 + rowB;

    // load Q tile with 0.125 scale folded in
    #pragma unroll
    for (int i = 0; i < 8; i++) {
        int idx = tid + i * 256;
        int r = idx >> 4, c = (idx & 15) * 4;
        float4 v = *(const float4*)(Qb + (size_t)(q0 + r) * D_SZ + c);
        v.x *= 0.125f; v.y *= 0.125f; v.z *= 0.125f; v.w *= 0.125f;
        *(float4*)(Qsh + r * ALD + c) = v;
    }

    float oacc[8][4];
    #pragma unroll
    for (int f = 0; f < 8; f++)
        #pragma unroll
        for (int e = 0; e < 4; e++) oacc[f][e] = 0.f;

    float laccA = 0.f, laccB = 0.f;   // lane-partial row sums (reduced at end)

    int kr = tid >> 4, kc = (tid & 15) * 4;   // K/V fill coords
    int nkt = 2 * qt + 2;

    for (int kt = 0; kt < nkt; ++kt) {
        int k0 = kt * AK;
        __syncthreads();                       // all warps done with prev K/V
        #pragma unroll
        for (int i = 0; i < 4; i++) {
            int r = kr + i * 16;
            cp_async16(Ksh + r * ALD + kc, Kb + (size_t)(k0 + r) * D_SZ + kc);
            cp_async16(Vsh + r * ALD + kc, Vb + (size_t)(k0 + r) * D_SZ + kc);
        }
        cp_commit();
        cp_wait<0>();
        __syncthreads();                       // K/V tile visible

        // ---- S = (Q*0.125) @ K^T, in registers ----
        float sacc[8][4];
        #pragma unroll
        for (int f = 0; f < 8; f++)
            #pragma unroll
            for (int e = 0; e < 4; e++) sacc[f][e] = 0.f;

        #pragma unroll
        for (int kk = 0; kk < 64; kk += 8) {
            uint32_t a[4];
            a[0] = __float_as_uint(Qsh[rowA * ALD + kk + t]);
            a[1] = __float_as_uint(Qsh[rowB * ALD + kk + t]);
            a[2] = __float_as_uint(Qsh[rowA * ALD + kk + t + 4]);
            a[3] = __float_as_uint(Qsh[rowB * ALD + kk + t + 4]);
            #pragma unroll
            for (int f = 0; f < 8; f++) {
                uint32_t bb[2];
                bb[0] = __float_as_uint(Ksh[(f * 8 + g) * ALD + kk + t]);
                bb[1] = __float_as_uint(Ksh[(f * 8 + g) * ALD + kk + t + 4]);
                mma_tf32(sacc[f], a, bb);
            }
        }

        // ---- softmax numerator in registers (mask, exp, tf32-round, partial sums)
        #pragma unroll
        for (int f = 0; f < 8; f++) {
            int c0 = k0 + f * 8 + 2 * t;
            float p0 = (c0     <= qiA) ? __expf(fminf(sacc[f][0], 60.f)) : 0.f;
            float p1 = (c0 + 1 <= qiA) ? __expf(fminf(sacc[f][1], 60.f)) : 0.f;
            float p2 = (c0     <= qiB) ? __expf(fminf(sacc[f][2], 60.f)) : 0.f;
            float p3 = (c0 + 1 <= qiB) ? __expf(fminf(sacc[f][3], 60.f)) : 0.f;
            p0 = wmma::__float_to_tf32(p0);
            p1 = wmma::__float_to_tf32(p1);
            p2 = wmma::__float_to_tf32(p2);
            p3 = wmma::__float_to_tf32(p3);
            laccA += p0 + p1;
            laccB += p2 + p3;
            sacc[f][0] = p0; sacc[f][1] = p1; sacc[f][2] = p2; sacc[f][3] = p3;
        }

        __syncwarp();   // prior PV loads from Ssh complete before overwrite
        #pragma unroll
        for (int f = 0; f < 8; f++) {
            *(float2*)(Ssh + rowA * ALD + f * 8 + 2 * t) = make_float2(sacc[f][0], sacc[f][1]);
            *(float2*)(Ssh + rowB * ALD + f * 8 + 2 * t) = make_float2(sacc[f][2], sacc[f][3]);
        }
        __syncwarp();   // P visible to all lanes of this warp

        // ---- O += P @ V ----
        #pragma unroll
        for (int kk = 0; kk < 64; kk += 8) {
            uint32_t a[4];
            a[0] = __float_as_uint(Ssh[rowA * ALD + kk + t]);
            a[1] = __float_as_uint(Ssh[rowB * ALD + kk + t]);
            a[2] = __float_as_uint(Ssh[rowA * ALD + kk + t + 4]);
            a[3] = __float_as_uint(Ssh[rowB * ALD + kk + t + 4]);
            #pragma unroll
            for (int f = 0; f < 8; f++) {
                uint32_t bb[2];
                bb[0] = __float_as_uint(Vsh[(kk + t)     * ALD + f * 8 + g]);
                bb[1] = __float_as_uint(Vsh[(kk + t + 4) * ALD + f * 8 + g]);
                mma_tf32(oacc[f], a, bb);
            }
        }
    }

    // ---- row-sum reduction across the quad, normalize O in registers ----
    laccA += __shfl_xor_sync(0xffffffffu, laccA, 1);
    laccA += __shfl_xor_sync(0xffffffffu, laccA, 2);
    laccB += __shfl_xor_sync(0xffffffffu, laccB, 1);
    laccB += __shfl_xor_sync(0xffffffffu, laccB, 2);
    float invA = 1.0f / laccA;
    float invB = 1.0f / laccB;

    __syncwarp();
    #pragma unroll
    for (int f = 0; f < 8; f++) {
        float2 vA, vB;
        vA.x = wmma::__float_to_tf32(oacc[f][0] * invA);
        vA.y = wmma::__float_to_tf32(oacc[f][1] * invA);
        vB.x = wmma::__float_to_tf32(oacc[f][2] * invB);
        vB.y = wmma::__float_to_tf32(oacc[f][3] * invB);
        *(float2*)(Ssh + rowA * ALD + f * 8 + 2 * t) = vA;
        *(float2*)(Ssh + rowB * ALD + f * 8 + 2 * t) = vB;
    }
    __syncwarp();

    // coalesced write of this warp's 16 rows
    #pragma unroll
    for (int i = 0; i < 8; i++) {
        int idx = lane + i * 32;
        int rr = r0 + (idx >> 4), cc = (idx & 15) * 4;
        float4 v = *(float4*)(Ssh + rr * ALD + cc);
        *(float4*)(g_ao + (size_t)(b * T_SZ + q0 + rr) * C_SZ + h * D_SZ + cc) = v;
    }
}

// ---------------- launch ----------------
extern "C" void kernel_launch(void* const* d_in, const int* in_sizes, int n_in,
                              void* d_out, int out_size)
{
    const float* x    = (const float*)d_in[0];
    const float* Wqkv = (const float*)d_in[1];
    const float* bqkv = (const float*)d_in[2];
    const float* Wout = (const float*)d_in[3];
    const float* bout = (const float*)d_in[4];
    float* out = (float*)d_out;

    cudaFuncSetAttribute(gemm_tf32,
                         cudaFuncAttributeMaxDynamicSharedMemorySize, GEMM_SMEM_BYTES);
    cudaFuncSetAttribute(attn_kernel,
                         cudaFuncAttributeMaxDynamicSharedMemorySize, ATT_SMEM_BYTES);

    static float *p_xr = nullptr, *p_wqkv = nullptr, *p_wout = nullptr;
    if (!p_xr) {
        cudaGetSymbolAddress((void**)&p_xr,   g_xr);
        cudaGetSymbolAddress((void**)&p_wqkv, g_wqkv);
        cudaGetSymbolAddress((void**)&p_wout, g_wout);
    }

    // prep: round operands to tf32 once
    round_copy<<<(M_SZ * C_SZ / 4 + 255) / 256, 256>>>(x, p_xr, M_SZ * C_SZ / 4);
    round_copy<<<(3 * C_SZ * C_SZ / 4 + 255) / 256, 256>>>(Wqkv, p_wqkv, 3 * C_SZ * C_SZ / 4);
    round_copy<<<(C_SZ * C_SZ / 4 + 255) / 256, 256>>>(Wout, p_wout, C_SZ * C_SZ / 4);

    // 1) QKV projection
    dim3 g1(3 * C_SZ / BN, M_SZ / BM);   // (24, 32)
    gemm_tf32<<<g1, 256, GEMM_SMEM_BYTES>>>(bqkv, nullptr, M_SZ, 3 * C_SZ, C_SZ, 0);

    // 2) causal flash attention
    dim3 g2(T_SZ / AQ, B_SZ * H_SZ);     // (16, 64)
    attn_kernel<<<g2, 256, ATT_SMEM_BYTES>>>();

    // 3) output projection
    dim3 g3(C_SZ / BN, M_SZ / BM);       // (8, 32)
    gemm_tf32<<<g3, 256, GEMM_SMEM_BYTES>>>(bout, out, M_SZ, C_SZ, C_SZ, 1);
}

// round 11
// speedup vs baseline: 2.2415x; 1.6088x over previous
#include <cuda_runtime.h>
#include <mma.h>
#include <math.h>
#include <stdint.h>

using namespace nvcuda;

#define B_SZ 4
#define T_SZ 2048
#define C_SZ 1024
#define H_SZ 16
#define D_SZ 64
#define M_SZ (B_SZ * T_SZ)   // 8192

// ---------------- scratch (static device globals; no allocation) ----------------
__device__ float g_q[(size_t)B_SZ * H_SZ * T_SZ * D_SZ];   // [B,H,T,D] tf32-rounded
__device__ float g_k[(size_t)B_SZ * H_SZ * T_SZ * D_SZ];
__device__ float g_v[(size_t)B_SZ * H_SZ * T_SZ * D_SZ];
__device__ float g_ao[(size_t)B_SZ * T_SZ * C_SZ];         // attention out, tf32-rounded
__device__ float g_xr[(size_t)M_SZ * C_SZ];                // x, tf32-rounded
__device__ float g_wqkv[(size_t)C_SZ * 3 * C_SZ];          // W_qkv, tf32-rounded
__device__ float g_wout[(size_t)C_SZ * C_SZ];              // W_out, tf32-rounded

// ---------------- cp.async helpers ----------------
__device__ __forceinline__ void cp_async16(void* smem, const void* gmem) {
    uint32_t s = (uint32_t)__cvta_generic_to_shared(smem);
    asm volatile("cp.async.cg.shared.global [%0], [%1], 16;\n" :: "r"(s), "l"(gmem));
}
__device__ __forceinline__ void cp_commit() {
    asm volatile("cp.async.commit_group;\n");
}
template<int N>
__device__ __forceinline__ void cp_wait() {
    asm volatile("cp.async.wait_group %0;\n" :: "n"(N));
}

// ---------------- raw tf32 mma (PTX-defined fragment layout) ----------------
__device__ __forceinline__ void mma_tf32(float* c, const uint32_t* a, const uint32_t* b) {
    asm volatile(
        "mma.sync.aligned.m16n8k8.row.col.f32.tf32.tf32.f32 "
        "{%0,%1,%2,%3}, {%4,%5,%6,%7}, {%8,%9}, {%0,%1,%2,%3};\n"
        : "+f"(c[0]), "+f"(c[1]), "+f"(c[2]), "+f"(c[3])
        : "r"(a[0]), "r"(a[1]), "r"(a[2]), "r"(a[3]), "r"(b[0]), "r"(b[1]));
}

// ---------------- prep: round to tf32 in gmem ----------------
__global__ void round_copy(const float* __restrict__ src, float* __restrict__ dst, int n4) {
    int i = blockIdx.x * blockDim.x + threadIdx.x;
    if (i < n4) {
        float4 v = ((const float4*)src)[i];
        v.x = wmma::__float_to_tf32(v.x);
        v.y = wmma::__float_to_tf32(v.y);
        v.z = wmma::__float_to_tf32(v.z);
        v.w = wmma::__float_to_tf32(v.w);
        ((float4*)dst)[i] = v;
    }
}

// ---------------- GEMM v3: raw m16n8k8 mma, 128x128 CTA, 4 warps of 64x64 -------
// mode 0: A = g_xr [M,K], B = g_wqkv [K,3C]; scatter into g_q/g_k/g_v (round tf32)
// mode 1: A = g_ao [M,K], B = g_wout [K,C]; write Cout row-major
#define BM 128
#define BN 128
#define BK 32
#define GS 3
#define LDA (BK + 4)    // 36
#define LDB (BN + 4)    // 132
#define A_STG (BM * LDA)          // 4608 floats
#define B_STG (BK * LDB)          // 4224 floats
#define GEMM_SMEM_BYTES (GS * (A_STG + B_STG) * 4)   // 105984 B -> 2 CTAs/SM

__global__ void __launch_bounds__(128, 2) gemm_tf32(
    const float* __restrict__ bias, float* __restrict__ Cout,
    int M, int N, int K, int mode)
{
    extern __shared__ float gsm[];
    float* Ash = gsm;                   // GS stages
    float* Bsh = gsm + GS * A_STG;      // GS stages

    const float* Aptr = (mode == 1) ? g_ao : g_xr;
    const float* Bm   = (mode == 1) ? g_wout : g_wqkv;

    int tid  = threadIdx.x;
    int warp = tid >> 5;    // 0..3
    int lane = tid & 31;
    int wm = warp >> 1;     // 0..1 (64-row band)
    int wn = warp & 1;      // 0..1 (64-col band)
    int g  = lane >> 2;     // 0..7
    int t  = lane & 3;      // 0..3
    int m0 = blockIdx.y * BM;
    int n0 = blockIdx.x * BN;

    // accumulators: 4 m16-tiles x 8 n8-frags x 4 regs
    float acc[4][8][4];
    #pragma unroll
    for (int i = 0; i < 4; i++)
        #pragma unroll
        for (int f = 0; f < 8; f++)
            #pragma unroll
            for (int e = 0; e < 4; e++) acc[i][f][e] = 0.f;

    // per-thread load coordinates (128 threads)
    int ar = tid >> 3,  ac = (tid & 7)  * 4;   // A: rows 0..15 (+16i), 8 f4/row
    int br = tid >> 5,  bc = (tid & 31) * 4;   // B: rows 0..3 (+4i), 32 f4/row

    auto load_tile = [&](int stage, int k0) {
        float* As = Ash + stage * A_STG;
        float* Bs = Bsh + stage * B_STG;
        #pragma unroll
        for (int i = 0; i < 8; i++) {
            int r = ar + i * 16;
            cp_async16(As + r * LDA + ac, Aptr + (size_t)(m0 + r) * K + k0 + ac);
        }
        #pragma unroll
        for (int i = 0; i < 8; i++) {
            int r = br + i * 4;
            cp_async16(Bs + r * LDB + bc, Bm + (size_t)(k0 + r) * N + n0 + bc);
        }
        cp_commit();
    };

    int KT = K / BK;
    load_tile(0, 0);
    load_tile(1, BK);

    for (int kt = 0; kt < KT; ++kt) {
        cp_wait<1>();
        __syncthreads();
        if (kt + 2 < KT) load_tile((kt + 2) % GS, (kt + 2) * BK);
        else             cp_commit();

        float* As = Ash + (kt % GS) * A_STG;
        float* Bs = Bsh + (kt % GS) * B_STG;

        #pragma unroll
        for (int kk = 0; kk < BK; kk += 8) {
            // A-fragments for the warp's 4 m16-tiles (conflict-free: bank 4g+t)
            uint32_t a[4][4];
            #pragma unroll
            for (int i = 0; i < 4; i++) {
                int rA = wm * 64 + i * 16 + g;
                a[i][0] = __float_as_uint(As[(rA    ) * LDA + kk + t]);
                a[i][1] = __float_as_uint(As[(rA + 8) * LDA + kk + t]);
                a[i][2] = __float_as_uint(As[(rA    ) * LDA + kk + t + 4]);
                a[i][3] = __float_as_uint(As[(rA + 8) * LDA + kk + t + 4]);
            }
            // per n8-frag: 2 B regs, 4 mmas (conflict-free: bank 4t+g)
            #pragma unroll
            for (int f = 0; f < 8; f++) {
                uint32_t bb[2];
                int nB = wn * 64 + f * 8 + g;
                bb[0] = __float_as_uint(Bs[(kk + t)     * LDB + nB]);
                bb[1] = __float_as_uint(Bs[(kk + t + 4) * LDB + nB]);
                #pragma unroll
                for (int i = 0; i < 4; i++)
                    mma_tf32(acc[i][f], a[i], bb);
            }
        }
    }
    __syncthreads();   // protect smem reuse by epilogue staging

    // Epilogue: per m16-tile, stage 16x64 through smem (pitch 68), then
    // coalesced float4 read + bias + scatter/store.
    float* stg = Ash + warp * 1152;   // 4 warps x 1152 floats inside stage 0 (4608)
    #pragma unroll
    for (int i = 0; i < 4; i++) {
        #pragma unroll
        for (int f = 0; f < 8; f++) {
            *(float2*)(stg + (g    ) * 68 + f * 8 + 2 * t) = make_float2(acc[i][f][0], acc[i][f][1]);
            *(float2*)(stg + (g + 8) * 68 + f * 8 + 2 * t) = make_float2(acc[i][f][2], acc[i][f][3]);
        }
        __syncwarp();
        #pragma unroll
        for (int e = 0; e < 8; e++) {
            int idx = lane + e * 32;          // 0..255 over 16 rows x 16 f4
            int rr = idx >> 4, cc = (idx & 15) * 4;
            int m = m0 + wm * 64 + i * 16 + rr;
            int n = n0 + wn * 64 + cc;
            float4 v  = *(float4*)(stg + rr * 68 + cc);
            float4 bv = *(const float4*)(bias + n);
            v.x += bv.x; v.y += bv.y; v.z += bv.z; v.w += bv.w;
            if (mode == 0) {
                int third = n >> 10, c = n & 1023;
                int h = c >> 6, d = c & 63;
                int b = m >> 11, tt = m & 2047;
                float* dst = (third == 0) ? g_q : (third == 1) ? g_k : g_v;
                v.x = wmma::__float_to_tf32(v.x);
                v.y = wmma::__float_to_tf32(v.y);
                v.z = wmma::__float_to_tf32(v.z);
                v.w = wmma::__float_to_tf32(v.w);
                *(float4*)(dst + (((size_t)(b * H_SZ + h)) * T_SZ + tt) * D_SZ + d) = v;
            } else {
                *(float4*)(Cout + (size_t)m * N + n) = v;
            }
        }
        __syncwarp();
    }
}

// ---------------- Flash attention, raw m16n8k8 mma, register softmax -------------
// (unchanged from R10 — ~370us known-good)
#define AQ 128
#define AK 64
#define ALD 68
#define ATT_SMEM_FLOATS (AQ * ALD + AK * ALD + AK * ALD + AQ * ALD)
#define ATT_SMEM_BYTES  (ATT_SMEM_FLOATS * 4)   // 104448 B -> 2 CTAs/SM

__global__ void __launch_bounds__(256, 2) attn_kernel()
{
    extern __shared__ float smbuf[];
    float* Qsh = smbuf;
    float* Ksh = Qsh + AQ * ALD;
    float* Vsh = Ksh + AK * ALD;
    float* Ssh = Vsh + AK * ALD;

    int qt = gridDim.x - 1 - blockIdx.x;   // longest tiles first
    int q0 = qt * AQ;
    int bh = blockIdx.y;
    int b = bh >> 4, h = bh & 15;

    const float* Qb = g_q + (size_t)bh * T_SZ * D_SZ;
    const float* Kb = g_k + (size_t)bh * T_SZ * D_SZ;
    const float* Vb = g_v + (size_t)bh * T_SZ * D_SZ;

    int tid  = threadIdx.x;
    int warp = tid >> 5;
    int lane = tid & 31;
    int r0 = warp * 16;
    int g = lane >> 2;
    int t = lane & 3;
    int rowA = r0 + g, rowB = rowA + 8;
    int qiA = q0 + rowA, qiB = q0 + rowB;

    // load Q tile with 0.125 scale folded in
    #pragma unroll
    for (int i = 0; i < 8; i++) {
        int idx = tid + i * 256;
        int r = idx >> 4, c = (idx & 15) * 4;
        float4 v = *(const float4*)(Qb + (size_t)(q0 + r) * D_SZ + c);
        v.x *= 0.125f; v.y *= 0.125f; v.z *= 0.125f; v.w *= 0.125f;
        *(float4*)(Qsh + r * ALD + c) = v;
    }

    float oacc[8][4];
    #pragma unroll
    for (int f = 0; f < 8; f++)
        #pragma unroll
        for (int e = 0; e < 4; e++) oacc[f][e] = 0.f;

    float laccA = 0.f, laccB = 0.f;

    int kr = tid >> 4, kc = (tid & 15) * 4;
    int nkt = 2 * qt + 2;

    for (int kt = 0; kt < nkt; ++kt) {
        int k0 = kt * AK;
        __syncthreads();
        #pragma unroll
        for (int i = 0; i < 4; i++) {
            int r = kr + i * 16;
            cp_async16(Ksh + r * ALD + kc, Kb + (size_t)(k0 + r) * D_SZ + kc);
            cp_async16(Vsh + r * ALD + kc, Vb + (size_t)(k0 + r) * D_SZ + kc);
        }
        cp_commit();
        cp_wait<0>();
        __syncthreads();

        // ---- S = (Q*0.125) @ K^T, in registers ----
        float sacc[8][4];
        #pragma unroll
        for (int f = 0; f < 8; f++)
            #pragma unroll
            for (int e = 0; e < 4; e++) sacc[f][e] = 0.f;

        #pragma unroll
        for (int kk = 0; kk < 64; kk += 8) {
            uint32_t a[4];
            a[0] = __float_as_uint(Qsh[rowA * ALD + kk + t]);
            a[1] = __float_as_uint(Qsh[rowB * ALD + kk + t]);
            a[2] = __float_as_uint(Qsh[rowA * ALD + kk + t + 4]);
            a[3] = __float_as_uint(Qsh[rowB * ALD + kk + t + 4]);
            #pragma unroll
            for (int f = 0; f < 8; f++) {
                uint32_t bb[2];
                bb[0] = __float_as_uint(Ksh[(f * 8 + g) * ALD + kk + t]);
                bb[1] = __float_as_uint(Ksh[(f * 8 + g) * ALD + kk + t + 4]);
                mma_tf32(sacc[f], a, bb);
            }
        }

        // ---- softmax numerator in registers ----
        #pragma unroll
        for (int f = 0; f < 8; f++) {
            int c0 = k0 + f * 8 + 2 * t;
            float p0 = (c0     <= qiA) ? __expf(fminf(sacc[f][0], 60.f)) : 0.f;
            float p1 = (c0 + 1 <= qiA) ? __expf(fminf(sacc[f][1], 60.f)) : 0.f;
            float p2 = (c0     <= qiB) ? __expf(fminf(sacc[f][2], 60.f)) : 0.f;
            float p3 = (c0 + 1 <= qiB) ? __expf(fminf(sacc[f][3], 60.f)) : 0.f;
            p0 = wmma::__float_to_tf32(p0);
            p1 = wmma::__float_to_tf32(p1);
            p2 = wmma::__float_to_tf32(p2);
            p3 = wmma::__float_to_tf32(p3);
            laccA += p0 + p1;
            laccB += p2 + p3;
            sacc[f][0] = p0; sacc[f][1] = p1; sacc[f][2] = p2; sacc[f][3] = p3;
        }

        __syncwarp();
        #pragma unroll
        for (int f = 0; f < 8; f++) {
            *(float2*)(Ssh + rowA * ALD + f * 8 + 2 * t) = make_float2(sacc[f][0], sacc[f][1]);
            *(float2*)(Ssh + rowB * ALD + f * 8 + 2 * t) = make_float2(sacc[f][2], sacc[f][3]);
        }
        __syncwarp();

        // ---- O += P @ V ----
        #pragma unroll
        for (int kk = 0; kk < 64; kk += 8) {
            uint32_t a[4];
            a[0] = __float_as_uint(Ssh[rowA * ALD + kk + t]);
            a[1] = __float_as_uint(Ssh[rowB * ALD + kk + t]);
            a[2] = __float_as_uint(Ssh[rowA * ALD + kk + t + 4]);
            a[3] = __float_as_uint(Ssh[rowB * ALD + kk + t + 4]);
            #pragma unroll
            for (int f = 0; f < 8; f++) {
                uint32_t bb[2];
                bb[0] = __float_as_uint(Vsh[(kk + t)     * ALD + f * 8 + g]);
                bb[1] = __float_as_uint(Vsh[(kk + t + 4) * ALD + f * 8 + g]);
                mma_tf32(oacc[f], a, bb);
            }
        }
    }

    // ---- row-sum reduction across the quad, normalize O ----
    laccA += __shfl_xor_sync(0xffffffffu, laccA, 1);
    laccA += __shfl_xor_sync(0xffffffffu, laccA, 2);
    laccB += __shfl_xor_sync(0xffffffffu, laccB, 1);
    laccB += __shfl_xor_sync(0xffffffffu, laccB, 2);
    float invA = 1.0f / laccA;
    float invB = 1.0f / laccB;

    __syncwarp();
    #pragma unroll
    for (int f = 0; f < 8; f++) {
        float2 vA, vB;
        vA.x = wmma::__float_to_tf32(oacc[f][0] * invA);
        vA.y = wmma::__float_to_tf32(oacc[f][1] * invA);
        vB.x = wmma::__float_to_tf32(oacc[f][2] * invB);
        vB.y = wmma::__float_to_tf32(oacc[f][3] * invB);
        *(float2*)(Ssh + rowA * ALD + f * 8 + 2 * t) = vA;
        *(float2*)(Ssh + rowB * ALD + f * 8 + 2 * t) = vB;
    }
    __syncwarp();

    #pragma unroll
    for (int i = 0; i < 8; i++) {
        int idx = lane + i * 32;
        int rr = r0 + (idx >> 4), cc = (idx & 15) * 4;
        float4 v = *(float4*)(Ssh + rr * ALD + cc);
        *(float4*)(g_ao + (size_t)(b * T_SZ + q0 + rr) * C_SZ + h * D_SZ + cc) = v;
    }
}

// ---------------- launch ----------------
extern "C" void kernel_launch(void* const* d_in, const int* in_sizes, int n_in,
                              void* d_out, int out_size)
{
    const float* x    = (const float*)d_in[0];
    const float* Wqkv = (const float*)d_in[1];
    const float* bqkv = (const float*)d_in[2];
    const float* Wout = (const float*)d_in[3];
    const float* bout = (const float*)d_in[4];
    float* out = (float*)d_out;

    cudaFuncSetAttribute(gemm_tf32,
                         cudaFuncAttributeMaxDynamicSharedMemorySize, GEMM_SMEM_BYTES);
    cudaFuncSetAttribute(attn_kernel,
                         cudaFuncAttributeMaxDynamicSharedMemorySize, ATT_SMEM_BYTES);

    static float *p_xr = nullptr, *p_wqkv = nullptr, *p_wout = nullptr;
    if (!p_xr) {
        cudaGetSymbolAddress((void**)&p_xr,   g_xr);
        cudaGetSymbolAddress((void**)&p_wqkv, g_wqkv);
        cudaGetSymbolAddress((void**)&p_wout, g_wout);
    }

    // prep: round operands to tf32 once
    round_copy<<<(M_SZ * C_SZ / 4 + 255) / 256, 256>>>(x, p_xr, M_SZ * C_SZ / 4);
    round_copy<<<(3 * C_SZ * C_SZ / 4 + 255) / 256, 256>>>(Wqkv, p_wqkv, 3 * C_SZ * C_SZ / 4);
    round_copy<<<(C_SZ * C_SZ / 4 + 255) / 256, 256>>>(Wout, p_wout, C_SZ * C_SZ / 4);

    // 1) QKV projection
    dim3 g1(3 * C_SZ / BN, M_SZ / BM);   // (24, 64)
    gemm_tf32<<<g1, 128, GEMM_SMEM_BYTES>>>(bqkv, nullptr, M_SZ, 3 * C_SZ, C_SZ, 0);

    // 2) causal flash attention
    dim3 g2(T_SZ / AQ, B_SZ * H_SZ);     // (16, 64)
    attn_kernel<<<g2, 256, ATT_SMEM_BYTES>>>();

    // 3) output projection
    dim3 g3(C_SZ / BN, M_SZ / BM);       // (8, 64)
    gemm_tf32<<<g3, 128, GEMM_SMEM_BYTES>>>(bout, out, M_SZ, C_SZ, C_SZ, 1);
}

// round 12
// speedup vs baseline: 2.3667x; 1.0558x over previous
#include <cuda_runtime.h>
#include <mma.h>
#include <math.h>
#include <stdint.h>

using namespace nvcuda;

#define B_SZ 4
#define T_SZ 2048
#define C_SZ 1024
#define H_SZ 16
#define D_SZ 64
#define M_SZ (B_SZ * T_SZ)   // 8192

// ---------------- scratch (static device globals; no allocation) ----------------
__device__ float g_q[(size_t)B_SZ * H_SZ * T_SZ * D_SZ];   // [B,H,T,D] tf32-rounded
__device__ float g_k[(size_t)B_SZ * H_SZ * T_SZ * D_SZ];
__device__ float g_v[(size_t)B_SZ * H_SZ * T_SZ * D_SZ];
__device__ float g_ao[(size_t)B_SZ * T_SZ * C_SZ];         // attention out, tf32-rounded
__device__ float g_xr[(size_t)M_SZ * C_SZ];                // x, tf32-rounded
__device__ float g_wqkv[(size_t)C_SZ * 3 * C_SZ];          // W_qkv, tf32-rounded
__device__ float g_wout[(size_t)C_SZ * C_SZ];              // W_out, tf32-rounded

// ---------------- cp.async helpers ----------------
__device__ __forceinline__ void cp_async16(void* smem, const void* gmem) {
    uint32_t s = (uint32_t)__cvta_generic_to_shared(smem);
    asm volatile("cp.async.cg.shared.global [%0], [%1], 16;\n" :: "r"(s), "l"(gmem));
}
__device__ __forceinline__ void cp_commit() {
    asm volatile("cp.async.commit_group;\n");
}
template<int N>
__device__ __forceinline__ void cp_wait() {
    asm volatile("cp.async.wait_group %0;\n" :: "n"(N));
}

// ---------------- raw tf32 mma (PTX-defined fragment layout) ----------------
__device__ __forceinline__ void mma_tf32(float* c, const uint32_t* a, const uint32_t* b) {
    asm volatile(
        "mma.sync.aligned.m16n8k8.row.col.f32.tf32.tf32.f32 "
        "{%0,%1,%2,%3}, {%4,%5,%6,%7}, {%8,%9}, {%0,%1,%2,%3};\n"
        : "+f"(c[0]), "+f"(c[1]), "+f"(c[2]), "+f"(c[3])
        : "r"(a[0]), "r"(a[1]), "r"(a[2]), "r"(a[3]), "r"(b[0]), "r"(b[1]));
}

// ---------------- prep: round all three operand arrays to tf32 (one launch) -----
#define XR_F4   (M_SZ * C_SZ / 4)            // 2,097,152
#define WQKV_F4 (3 * C_SZ * C_SZ / 4)        //   786,432
#define WOUT_F4 (C_SZ * C_SZ / 4)            //   262,144
#define PREP_F4 (XR_F4 + WQKV_F4 + WOUT_F4)  // 3,145,728

__global__ void round_all(const float4* __restrict__ x,
                          const float4* __restrict__ wqkv,
                          const float4* __restrict__ wout)
{
    int i = blockIdx.x * blockDim.x + threadIdx.x;
    if (i >= PREP_F4) return;
    const float4* src;
    float4* dst;
    if (i < XR_F4) {
        src = x + i;                     dst = (float4*)g_xr + i;
    } else if (i < XR_F4 + WQKV_F4) {
        int j = i - XR_F4;
        src = wqkv + j;                  dst = (float4*)g_wqkv + j;
    } else {
        int j = i - XR_F4 - WQKV_F4;
        src = wout + j;                  dst = (float4*)g_wout + j;
    }
    float4 v = *src;
    v.x = wmma::__float_to_tf32(v.x);
    v.y = wmma::__float_to_tf32(v.y);
    v.z = wmma::__float_to_tf32(v.z);
    v.w = wmma::__float_to_tf32(v.w);
    *dst = v;
}

// ---------------- GEMM v3b: raw m16n8k8 mma, 128x128 CTA, GS=2, 3 CTAs/SM -------
// mode 0: A = g_xr [M,K], B = g_wqkv [K,3C]; scatter into g_q/g_k/g_v (round tf32)
// mode 1: A = g_ao [M,K], B = g_wout [K,C]; write Cout row-major
#define BM 128
#define BN 128
#define BK 32
#define GS 2
#define LDA (BK + 4)    // 36
#define LDB (BN + 4)    // 132
#define A_STG (BM * LDA)          // 4608 floats
#define B_STG (BK * LDB)          // 4224 floats
#define GEMM_SMEM_BYTES (GS * (A_STG + B_STG) * 4)   // 70656 B -> 3 CTAs/SM

__global__ void __launch_bounds__(128, 3) gemm_tf32(
    const float* __restrict__ bias, float* __restrict__ Cout,
    int M, int N, int K, int mode)
{
    extern __shared__ float gsm[];
    float* Ash = gsm;                   // GS stages
    float* Bsh = gsm + GS * A_STG;      // GS stages

    const float* Aptr = (mode == 1) ? g_ao : g_xr;
    const float* Bm   = (mode == 1) ? g_wout : g_wqkv;

    int tid  = threadIdx.x;
    int warp = tid >> 5;    // 0..3
    int lane = tid & 31;
    int wm = warp >> 1;     // 0..1 (64-row band)
    int wn = warp & 1;      // 0..1 (64-col band)
    int g  = lane >> 2;     // 0..7
    int t  = lane & 3;      // 0..3
    int m0 = blockIdx.y * BM;
    int n0 = blockIdx.x * BN;

    // accumulators: 4 m16-tiles x 8 n8-frags x 4 regs
    float acc[4][8][4];
    #pragma unroll
    for (int i = 0; i < 4; i++)
        #pragma unroll
        for (int f = 0; f < 8; f++)
            #pragma unroll
            for (int e = 0; e < 4; e++) acc[i][f][e] = 0.f;

    // per-thread load coordinates (128 threads)
    int ar = tid >> 3,  ac = (tid & 7)  * 4;   // A: rows 0..15 (+16i), 8 f4/row
    int br = tid >> 5,  bc = (tid & 31) * 4;   // B: rows 0..3 (+4i), 32 f4/row

    auto load_tile = [&](int stage, int k0) {
        float* As = Ash + stage * A_STG;
        float* Bs = Bsh + stage * B_STG;
        #pragma unroll
        for (int i = 0; i < 8; i++) {
            int r = ar + i * 16;
            cp_async16(As + r * LDA + ac, Aptr + (size_t)(m0 + r) * K + k0 + ac);
        }
        #pragma unroll
        for (int i = 0; i < 8; i++) {
            int r = br + i * 4;
            cp_async16(Bs + r * LDB + bc, Bm + (size_t)(k0 + r) * N + n0 + bc);
        }
        cp_commit();
    };

    int KT = K / BK;
    load_tile(0, 0);

    for (int kt = 0; kt < KT; ++kt) {
        __syncthreads();        // all warps done computing stage (kt-1)&1 (= (kt+1)&1)
        if (kt + 1 < KT) {
            load_tile((kt + 1) & 1, (kt + 1) * BK);
            cp_wait<1>();       // stage kt landed (kt+1 still flying)
        } else {
            cp_wait<0>();
        }
        __syncthreads();        // stage kt visible to every warp

        float* As = Ash + (kt & 1) * A_STG;
        float* Bs = Bsh + (kt & 1) * B_STG;

        #pragma unroll
        for (int kk = 0; kk < BK; kk += 8) {
            // A-fragments for the warp's 4 m16-tiles (conflict-free: bank 4g+t)
            uint32_t a[4][4];
            #pragma unroll
            for (int i = 0; i < 4; i++) {
                int rA = wm * 64 + i * 16 + g;
                a[i][0] = __float_as_uint(As[(rA    ) * LDA + kk + t]);
                a[i][1] = __float_as_uint(As[(rA + 8) * LDA + kk + t]);
                a[i][2] = __float_as_uint(As[(rA    ) * LDA + kk + t + 4]);
                a[i][3] = __float_as_uint(As[(rA + 8) * LDA + kk + t + 4]);
            }
            // per n8-frag: 2 B regs, 4 mmas (conflict-free: bank 4t+g)
            #pragma unroll
            for (int f = 0; f < 8; f++) {
                uint32_t bb[2];
                int nB = wn * 64 + f * 8 + g;
                bb[0] = __float_as_uint(Bs[(kk + t)     * LDB + nB]);
                bb[1] = __float_as_uint(Bs[(kk + t + 4) * LDB + nB]);
                #pragma unroll
                for (int i = 0; i < 4; i++)
                    mma_tf32(acc[i][f], a[i], bb);
            }
        }
    }
    __syncthreads();   // protect smem reuse by epilogue staging

    // Epilogue: per m16-tile, stage 16x64 through smem (pitch 68), then
    // coalesced float4 read + bias + scatter/store.
    float* stg = Ash + warp * 1152;   // 4 warps x 1152 floats inside stage 0 (4608)
    #pragma unroll
    for (int i = 0; i < 4; i++) {
        #pragma unroll
        for (int f = 0; f < 8; f++) {
            *(float2*)(stg + (g    ) * 68 + f * 8 + 2 * t) = make_float2(acc[i][f][0], acc[i][f][1]);
            *(float2*)(stg + (g + 8) * 68 + f * 8 + 2 * t) = make_float2(acc[i][f][2], acc[i][f][3]);
        }
        __syncwarp();
        #pragma unroll
        for (int e = 0; e < 8; e++) {
            int idx = lane + e * 32;          // 0..255 over 16 rows x 16 f4
            int rr = idx >> 4, cc = (idx & 15) * 4;
            int m = m0 + wm * 64 + i * 16 + rr;
            int n = n0 + wn * 64 + cc;
            float4 v  = *(float4*)(stg + rr * 68 + cc);
            float4 bv = *(const float4*)(bias + n);
            v.x += bv.x; v.y += bv.y; v.z += bv.z; v.w += bv.w;
            if (mode == 0) {
                int third = n >> 10, c = n & 1023;
                int h = c >> 6, d = c & 63;
                int b = m >> 11, tt = m & 2047;
                float* dst = (third == 0) ? g_q : (third == 1) ? g_k : g_v;
                v.x = wmma::__float_to_tf32(v.x);
                v.y = wmma::__float_to_tf32(v.y);
                v.z = wmma::__float_to_tf32(v.z);
                v.w = wmma::__float_to_tf32(v.w);
                *(float4*)(dst + (((size_t)(b * H_SZ + h)) * T_SZ + tt) * D_SZ + d) = v;
            } else {
                *(float4*)(Cout + (size_t)m * N + n) = v;
            }
        }
        __syncwarp();
    }
}

// ---------------- Flash attention, raw m16n8k8 mma, register softmax -------------
// (unchanged from R10/R11 — ~370us known-good)
#define AQ 128
#define AK 64
#define ALD 68
#define ATT_SMEM_FLOATS (AQ * ALD + AK * ALD + AK * ALD + AQ * ALD)
#define ATT_SMEM_BYTES  (ATT_SMEM_FLOATS * 4)   // 104448 B -> 2 CTAs/SM

__global__ void __launch_bounds__(256, 2) attn_kernel()
{
    extern __shared__ float smbuf[];
    float* Qsh = smbuf;
    float* Ksh = Qsh + AQ * ALD;
    float* Vsh = Ksh + AK * ALD;
    float* Ssh = Vsh + AK * ALD;

    int qt = gridDim.x - 1 - blockIdx.x;   // longest tiles first
    int q0 = qt * AQ;
    int bh = blockIdx.y;
    int b = bh >> 4, h = bh & 15;

    const float* Qb = g_q + (size_t)bh * T_SZ * D_SZ;
    const float* Kb = g_k + (size_t)bh * T_SZ * D_SZ;
    const float* Vb = g_v + (size_t)bh * T_SZ * D_SZ;

    int tid  = threadIdx.x;
    int warp = tid >> 5;
    int lane = tid & 31;
    int r0 = warp * 16;
    int g = lane >> 2;
    int t = lane & 3;
    int rowA = r0 + g, rowB = rowA + 8;
    int qiA = q0 + rowA, qiB = q0 + rowB;

    // load Q tile with 0.125 scale folded in
    #pragma unroll
    for (int i = 0; i < 8; i++) {
        int idx = tid + i * 256;
        int r = idx >> 4, c = (idx & 15) * 4;
        float4 v = *(const float4*)(Qb + (size_t)(q0 + r) * D_SZ + c);
        v.x *= 0.125f; v.y *= 0.125f; v.z *= 0.125f; v.w *= 0.125f;
        *(float4*)(Qsh + r * ALD + c) = v;
    }

    float oacc[8][4];
    #pragma unroll
    for (int f = 0; f < 8; f++)
        #pragma unroll
        for (int e = 0; e < 4; e++) oacc[f][e] = 0.f;

    float laccA = 0.f, laccB = 0.f;

    int kr = tid >> 4, kc = (tid & 15) * 4;
    int nkt = 2 * qt + 2;

    for (int kt = 0; kt < nkt; ++kt) {
        int k0 = kt * AK;
        __syncthreads();
        #pragma unroll
        for (int i = 0; i < 4; i++) {
            int r = kr + i * 16;
            cp_async16(Ksh + r * ALD + kc, Kb + (size_t)(k0 + r) * D_SZ + kc);
            cp_async16(Vsh + r * ALD + kc, Vb + (size_t)(k0 + r) * D_SZ + kc);
        }
        cp_commit();
        cp_wait<0>();
        __syncthreads();

        // ---- S = (Q*0.125) @ K^T, in registers ----
        float sacc[8][4];
        #pragma unroll
        for (int f = 0; f < 8; f++)
            #pragma unroll
            for (int e = 0; e < 4; e++) sacc[f][e] = 0.f;

        #pragma unroll
        for (int kk = 0; kk < 64; kk += 8) {
            uint32_t a[4];
            a[0] = __float_as_uint(Qsh[rowA * ALD + kk + t]);
            a[1] = __float_as_uint(Qsh[rowB * ALD + kk + t]);
            a[2] = __float_as_uint(Qsh[rowA * ALD + kk + t + 4]);
            a[3] = __float_as_uint(Qsh[rowB * ALD + kk + t + 4]);
            #pragma unroll
            for (int f = 0; f < 8; f++) {
                uint32_t bb[2];
                bb[0] = __float_as_uint(Ksh[(f * 8 + g) * ALD + kk + t]);
                bb[1] = __float_as_uint(Ksh[(f * 8 + g) * ALD + kk + t + 4]);
                mma_tf32(sacc[f], a, bb);
            }
        }

        // ---- softmax numerator in registers ----
        #pragma unroll
        for (int f = 0; f < 8; f++) {
            int c0 = k0 + f * 8 + 2 * t;
            float p0 = (c0     <= qiA) ? __expf(fminf(sacc[f][0], 60.f)) : 0.f;
            float p1 = (c0 + 1 <= qiA) ? __expf(fminf(sacc[f][1], 60.f)) : 0.f;
            float p2 = (c0     <= qiB) ? __expf(fminf(sacc[f][2], 60.f)) : 0.f;
            float p3 = (c0 + 1 <= qiB) ? __expf(fminf(sacc[f][3], 60.f)) : 0.f;
            p0 = wmma::__float_to_tf32(p0);
            p1 = wmma::__float_to_tf32(p1);
            p2 = wmma::__float_to_tf32(p2);
            p3 = wmma::__float_to_tf32(p3);
            laccA += p0 + p1;
            laccB += p2 + p3;
            sacc[f][0] = p0; sacc[f][1] = p1; sacc[f][2] = p2; sacc[f][3] = p3;
        }

        __syncwarp();
        #pragma unroll
        for (int f = 0; f < 8; f++) {
            *(float2*)(Ssh + rowA * ALD + f * 8 + 2 * t) = make_float2(sacc[f][0], sacc[f][1]);
            *(float2*)(Ssh + rowB * ALD + f * 8 + 2 * t) = make_float2(sacc[f][2], sacc[f][3]);
        }
        __syncwarp();

        // ---- O += P @ V ----
        #pragma unroll
        for (int kk = 0; kk < 64; kk += 8) {
            uint32_t a[4];
            a[0] = __float_as_uint(Ssh[rowA * ALD + kk + t]);
            a[1] = __float_as_uint(Ssh[rowB * ALD + kk + t]);
            a[2] = __float_as_uint(Ssh[rowA * ALD + kk + t + 4]);
            a[3] = __float_as_uint(Ssh[rowB * ALD + kk + t + 4]);
            #pragma unroll
            for (int f = 0; f < 8; f++) {
                uint32_t bb[2];
                bb[0] = __float_as_uint(Vsh[(kk + t)     * ALD + f * 8 + g]);
                bb[1] = __float_as_uint(Vsh[(kk + t + 4) * ALD + f * 8 + g]);
                mma_tf32(oacc[f], a, bb);
            }
        }
    }

    // ---- row-sum reduction across the quad, normalize O ----
    laccA += __shfl_xor_sync(0xffffffffu, laccA, 1);
    laccA += __shfl_xor_sync(0xffffffffu, laccA, 2);
    laccB += __shfl_xor_sync(0xffffffffu, laccB, 1);
    laccB += __shfl_xor_sync(0xffffffffu, laccB, 2);
    float invA = 1.0f / laccA;
    float invB = 1.0f / laccB;

    __syncwarp();
    #pragma unroll
    for (int f = 0; f < 8; f++) {
        float2 vA, vB;
        vA.x = wmma::__float_to_tf32(oacc[f][0] * invA);
        vA.y = wmma::__float_to_tf32(oacc[f][1] * invA);
        vB.x = wmma::__float_to_tf32(oacc[f][2] * invB);
        vB.y = wmma::__float_to_tf32(oacc[f][3] * invB);
        *(float2*)(Ssh + rowA * ALD + f * 8 + 2 * t) = vA;
        *(float2*)(Ssh + rowB * ALD + f * 8 + 2 * t) = vB;
    }
    __syncwarp();

    #pragma unroll
    for (int i = 0; i < 8; i++) {
        int idx = lane + i * 32;
        int rr = r0 + (idx >> 4), cc = (idx & 15) * 4;
        float4 v = *(float4*)(Ssh + rr * ALD + cc);
        *(float4*)(g_ao + (size_t)(b * T_SZ + q0 + rr) * C_SZ + h * D_SZ + cc) = v;
    }
}

// ---------------- launch ----------------
extern "C" void kernel_launch(void* const* d_in, const int* in_sizes, int n_in,
                              void* d_out, int out_size)
{
    const float* x    = (const float*)d_in[0];
    const float* Wqkv = (const float*)d_in[1];
    const float* bqkv = (const float*)d_in[2];
    const float* Wout = (const float*)d_in[3];
    const float* bout = (const float*)d_in[4];
    float* out = (float*)d_out;

    cudaFuncSetAttribute(gemm_tf32,
                         cudaFuncAttributeMaxDynamicSharedMemorySize, GEMM_SMEM_BYTES);
    cudaFuncSetAttribute(attn_kernel,
                         cudaFuncAttributeMaxDynamicSharedMemorySize, ATT_SMEM_BYTES);

    // prep: round all operands to tf32 in one launch
    round_all<<<(PREP_F4 + 255) / 256, 256>>>(
        (const float4*)x, (const float4*)Wqkv, (const float4*)Wout);

    // 1) QKV projection
    dim3 g1(3 * C_SZ / BN, M_SZ / BM);   // (24, 64)
    gemm_tf32<<<g1, 128, GEMM_SMEM_BYTES>>>(bqkv, nullptr, M_SZ, 3 * C_SZ, C_SZ, 0);

    // 2) causal flash attention
    dim3 g2(T_SZ / AQ, B_SZ * H_SZ);     // (16, 64)
    attn_kernel<<<g2, 256, ATT_SMEM_BYTES>>>();

    // 3) output projection
    dim3 g3(C_SZ / BN, M_SZ / BM);       // (8, 64)
    gemm_tf32<<<g3, 128, GEMM_SMEM_BYTES>>>(bout, out, M_SZ, C_SZ, C_SZ, 1);
}